// round 2
// baseline (speedup 1.0000x reference)
#include <cuda_runtime.h>
#include <math.h>

#define Bb 8
#define Nn 1024
#define Dd 768
#define Hh 12
#define DHh 64

typedef unsigned long long ull;

// Scratch (static device globals: allocation-free at kernel_launch time)
__device__ float g_Q[(size_t)Bb*Hh*Nn*DHh];   // [b,h,n,d]
__device__ float g_K[(size_t)Bb*Hh*Nn*DHh];
__device__ float g_V[(size_t)Bb*Hh*Nn*DHh];
__device__ float g_S[(size_t)Bb*Hh*Nn*Nn];    // logits -> (in place) post-mixed attn
__device__ float g_C[(size_t)Bb*Nn*Dd];       // context [b,n,h*64+d]

union F4U2 { float4 f; struct { ull lo, hi; } u; };

#define FFMA2(d, a, b) \
    asm("fma.rn.f32x2 %0, %1, %2, %0;" : "+l"(d) : "l"(a), "l"(b))

#define PACK2(d, a) \
    asm("mov.b64 %0, {%1, %1};" : "=l"(d) : "r"(__float_as_uint(a)))

// ---------------------------------------------------------------------------
// Compute cores. As: [128][20] floats (m-major, padded). Bs padded row-major.
// 8x8 microtile (acc[8][4] f32x2) or 8x4 microtile (acc[8][2] f32x2).
// ---------------------------------------------------------------------------
__device__ __forceinline__ void mma16_nn128(const float* __restrict__ As,
                                            const float* __restrict__ Bs,
                                            int ty4, int tx4, ull acc[8][4]) {
    #pragma unroll
    for (int k = 0; k < 16; ++k) {
        ull a2[8];
        #pragma unroll
        for (int i = 0; i < 4; ++i) {
            PACK2(a2[i],     As[(ty4 + i) * 20 + k]);
            PACK2(a2[4 + i], As[(64 + ty4 + i) * 20 + k]);
        }
        F4U2 b0, b1;
        b0.f = *(const float4*)&Bs[k * 132 + tx4];
        b1.f = *(const float4*)&Bs[k * 132 + 64 + tx4];
        ull b[4] = {b0.u.lo, b0.u.hi, b1.u.lo, b1.u.hi};
        #pragma unroll
        for (int m = 0; m < 8; ++m)
            #pragma unroll
            for (int n = 0; n < 4; ++n)
                FFMA2(acc[m][n], a2[m], b[n]);
    }
}

__device__ __forceinline__ void mma16_nn64(const float* __restrict__ As,
                                           const float* __restrict__ Bs,
                                           int ty4, int tx4, ull acc[8][2]) {
    #pragma unroll
    for (int k = 0; k < 16; ++k) {
        ull a2[8];
        #pragma unroll
        for (int i = 0; i < 4; ++i) {
            PACK2(a2[i],     As[(ty4 + i) * 20 + k]);
            PACK2(a2[4 + i], As[(64 + ty4 + i) * 20 + k]);
        }
        F4U2 b0;
        b0.f = *(const float4*)&Bs[k * 68 + tx4];
        ull b[2] = {b0.u.lo, b0.u.hi};
        #pragma unroll
        for (int m = 0; m < 8; ++m)
            #pragma unroll
            for (int n = 0; n < 2; ++n)
                FFMA2(acc[m][n], a2[m], b[n]);
    }
}

// ---------------------------------------------------------------------------
// K1: QKV projection. x[8192,768] @ [Wq | Wkv] -> g_Q/g_K/g_V [b,h,n,d]
// grid (18, 64): bx = n-tile over 2304 cols, by = m-tile over 8192 rows.
// ---------------------------------------------------------------------------
__global__ __launch_bounds__(256, 2) void k_qkv(const float* __restrict__ x,
                                                const float* __restrict__ Wq,
                                                const float* __restrict__ Wkv) {
    __shared__ float As[128 * 20];
    __shared__ float Bs[16 * 132];
    const int tid = threadIdx.x;
    const int bx = blockIdx.x, by = blockIdx.y;
    const int nglob = bx * 128;
    const float* Bp = (nglob < 768) ? (Wq + nglob) : (Wkv + (nglob - 768));
    const int ldb = (nglob < 768) ? 768 : 1536;

    const int tx4 = (tid & 15) * 4, ty4 = (tid >> 4) * 4;
    const int ar = tid >> 2, ak4 = (tid & 3) * 4;      // A loader
    const int bk = tid >> 4, bn4 = (tid & 15) * 4;     // B loader
    const float* Ap = x + ((size_t)by * 128 + ar) * 768 + ak4;

    ull acc[8][4];
    #pragma unroll
    for (int m = 0; m < 8; ++m)
        #pragma unroll
        for (int n = 0; n < 4; ++n) acc[m][n] = 0ull;

    float4 ra0 = *(const float4*)(Ap);
    float4 ra1 = *(const float4*)(Ap + (size_t)64 * 768);
    float4 rb0 = *(const float4*)(Bp + (size_t)bk * ldb + bn4);
    float4 rb1 = *(const float4*)(Bp + (size_t)bk * ldb + bn4 + 64);

    for (int kt = 0; kt < 48; ++kt) {
        *(float4*)&As[ar * 20 + ak4]        = ra0;
        *(float4*)&As[(ar + 64) * 20 + ak4] = ra1;
        *(float4*)&Bs[bk * 132 + bn4]       = rb0;
        *(float4*)&Bs[bk * 132 + bn4 + 64]  = rb1;
        __syncthreads();
        if (kt < 47) {
            ra0 = *(const float4*)(Ap + (kt + 1) * 16);
            ra1 = *(const float4*)(Ap + (size_t)64 * 768 + (kt + 1) * 16);
            rb0 = *(const float4*)(Bp + (size_t)((kt + 1) * 16 + bk) * ldb + bn4);
            rb1 = *(const float4*)(Bp + (size_t)((kt + 1) * 16 + bk) * ldb + bn4 + 64);
        }
        mma16_nn128(As, Bs, ty4, tx4, acc);
        __syncthreads();
    }

    #pragma unroll
    for (int half = 0; half < 2; ++half)
        #pragma unroll
        for (int i = 0; i < 4; ++i) {
            const int m = by * 128 + half * 64 + ty4 + i;
            const int b = m >> 10, nrow = m & 1023;
            #pragma unroll
            for (int g = 0; g < 2; ++g) {
                const int c = nglob + g * 64 + tx4;
                const int mat = c / 768;
                const int within = c - mat * 768;
                const int head = within >> 6, d = within & 63;
                float* G = (mat == 0) ? g_Q : (mat == 1) ? g_K : g_V;
                F4U2 v;
                v.u.lo = acc[half * 4 + i][g * 2];
                v.u.hi = acc[half * 4 + i][g * 2 + 1];
                *(float4*)(G + (((size_t)b * 12 + head) * 1024 + nrow) * 64 + d) = v.f;
            }
        }
}

// ---------------------------------------------------------------------------
// K2: raw dots = scale * Q @ K^T per (b,h). grid (8 jt, 8 it, 96 bh)
// ---------------------------------------------------------------------------
__global__ __launch_bounds__(256, 2) void k_dots() {
    __shared__ float As[128 * 20];
    __shared__ float Bs[16 * 132];
    const int tid = threadIdx.x;
    const int jt = blockIdx.x, it = blockIdx.y, bh = blockIdx.z;
    const float* Qp = g_Q + (size_t)bh * Nn * 64;
    const float* Kp = g_K + (size_t)bh * Nn * 64;
    float* Sp = g_S + (size_t)bh * Nn * Nn;

    const int tx4 = (tid & 15) * 4, ty4 = (tid >> 4) * 4;
    const int ar = tid >> 2, ak4 = (tid & 3) * 4;
    const float* Ap = Qp + ((size_t)it * 128 + ar) * 64 + ak4;
    const float* Bp = Kp + ((size_t)jt * 128 + ar) * 64 + ak4;

    ull acc[8][4];
    #pragma unroll
    for (int m = 0; m < 8; ++m)
        #pragma unroll
        for (int n = 0; n < 4; ++n) acc[m][n] = 0ull;

    float4 ra0 = *(const float4*)(Ap);
    float4 ra1 = *(const float4*)(Ap + 64 * 64);
    float4 rb0 = *(const float4*)(Bp);
    float4 rb1 = *(const float4*)(Bp + 64 * 64);

    for (int kt = 0; kt < 4; ++kt) {
        *(float4*)&As[ar * 20 + ak4]        = ra0;
        *(float4*)&As[(ar + 64) * 20 + ak4] = ra1;
        // transposed scatter of K into Bs[k][j]
        Bs[(ak4 + 0) * 132 + ar]      = rb0.x;
        Bs[(ak4 + 1) * 132 + ar]      = rb0.y;
        Bs[(ak4 + 2) * 132 + ar]      = rb0.z;
        Bs[(ak4 + 3) * 132 + ar]      = rb0.w;
        Bs[(ak4 + 0) * 132 + ar + 64] = rb1.x;
        Bs[(ak4 + 1) * 132 + ar + 64] = rb1.y;
        Bs[(ak4 + 2) * 132 + ar + 64] = rb1.z;
        Bs[(ak4 + 3) * 132 + ar + 64] = rb1.w;
        __syncthreads();
        if (kt < 3) {
            ra0 = *(const float4*)(Ap + (kt + 1) * 16);
            ra1 = *(const float4*)(Ap + 64 * 64 + (kt + 1) * 16);
            rb0 = *(const float4*)(Bp + (kt + 1) * 16);
            rb1 = *(const float4*)(Bp + 64 * 64 + (kt + 1) * 16);
        }
        mma16_nn128(As, Bs, ty4, tx4, acc);
        __syncthreads();
    }

    const float scale = 0.125f;
    #pragma unroll
    for (int half = 0; half < 2; ++half)
        #pragma unroll
        for (int i = 0; i < 4; ++i) {
            const int m = it * 128 + half * 64 + ty4 + i;
            #pragma unroll
            for (int g = 0; g < 2; ++g) {
                F4U2 v;
                v.u.lo = acc[half * 4 + i][g * 2];
                v.u.hi = acc[half * 4 + i][g * 2 + 1];
                v.f.x *= scale; v.f.y *= scale; v.f.z *= scale; v.f.w *= scale;
                *(float4*)(Sp + (size_t)m * 1024 + jt * 128 + g * 64 + tx4) = v.f;
            }
        }
}

// ---------------------------------------------------------------------------
// K3: talking-heads: mix_pre -> softmax -> mix_post, fused, in-place on g_S.
// ---------------------------------------------------------------------------
__global__ __launch_bounds__(256) void k_mixsoft(const float* __restrict__ mix_pre,
                                                 const float* __restrict__ mix_post) {
    __shared__ float raw[12 * 512];
    __shared__ float pre[144], post[144];
    __shared__ float wred[96];
    __shared__ float gstat[24];
    const int t = threadIdx.x;
    const int b = blockIdx.x >> 10, i = blockIdx.x & 1023;
    if (t < 144) { pre[t] = mix_pre[t]; post[t] = mix_post[t]; }
    const size_t rowbase = (size_t)b * 12 * 1048576 + (size_t)i * 1024;

    float mx[12][4];
    #pragma unroll
    for (int g = 0; g < 12; ++g)
        mx[g][0] = mx[g][1] = mx[g][2] = mx[g][3] = 0.f;

    #pragma unroll
    for (int c = 0; c < 2; ++c) {
        __syncthreads();
        #pragma unroll
        for (int u = 0; u < 24; ++u) {
            int idx = u * 256 + t;
            int h = idx >> 9, j = idx & 511;
            raw[idx] = g_S[rowbase + (size_t)h * 1048576 + c * 512 + j];
        }
        __syncthreads();
        float rv[12][2];
        #pragma unroll
        for (int h = 0; h < 12; ++h) {
            rv[h][0] = raw[h * 512 + t];
            rv[h][1] = raw[h * 512 + t + 256];
        }
        #pragma unroll
        for (int g = 0; g < 12; ++g) {
            float a0 = mx[g][c * 2], a1 = mx[g][c * 2 + 1];
            #pragma unroll
            for (int h = 0; h < 12; ++h) {
                float p = pre[h * 12 + g];
                a0 += rv[h][0] * p;
                a1 += rv[h][1] * p;
            }
            mx[g][c * 2] = a0; mx[g][c * 2 + 1] = a1;
        }
    }

    const int lane = t & 31, wid = t >> 5;
    #pragma unroll
    for (int g = 0; g < 12; ++g) {
        float m = fmaxf(fmaxf(mx[g][0], mx[g][1]), fmaxf(mx[g][2], mx[g][3]));
        #pragma unroll
        for (int o = 16; o > 0; o >>= 1) m = fmaxf(m, __shfl_xor_sync(0xffffffffu, m, o));
        if (lane == 0) wred[g * 8 + wid] = m;
    }
    __syncthreads();
    if (t < 12) {
        float m = wred[t * 8];
        #pragma unroll
        for (int w = 1; w < 8; ++w) m = fmaxf(m, wred[t * 8 + w]);
        gstat[t] = m;
    }
    __syncthreads();
    #pragma unroll
    for (int g = 0; g < 12; ++g) {
        float mg = gstat[g];
        float s = 0.f;
        #pragma unroll
        for (int r = 0; r < 4; ++r) { mx[g][r] = __expf(mx[g][r] - mg); s += mx[g][r]; }
        #pragma unroll
        for (int o = 16; o > 0; o >>= 1) s += __shfl_xor_sync(0xffffffffu, s, o);
        if (lane == 0) wred[g * 8 + wid] = s;
    }
    __syncthreads();
    if (t < 12) {
        float s = 0.f;
        #pragma unroll
        for (int w = 0; w < 8; ++w) s += wred[t * 8 + w];
        gstat[12 + t] = 1.0f / s;
    }
    __syncthreads();
    #pragma unroll
    for (int g = 0; g < 12; ++g) {
        float inv = gstat[12 + g];
        #pragma unroll
        for (int r = 0; r < 4; ++r) mx[g][r] *= inv;
    }
    #pragma unroll
    for (int h = 0; h < 12; ++h) {
        float o0 = 0.f, o1 = 0.f, o2 = 0.f, o3 = 0.f;
        #pragma unroll
        for (int g = 0; g < 12; ++g) {
            float p = post[g * 12 + h];
            o0 += mx[g][0] * p; o1 += mx[g][1] * p;
            o2 += mx[g][2] * p; o3 += mx[g][3] * p;
        }
        float* dst = g_S + rowbase + (size_t)h * 1048576;
        dst[t]       = o0; dst[t + 256] = o1;
        dst[t + 512] = o2; dst[t + 768] = o3;
    }
}

// ---------------------------------------------------------------------------
// K4: O = attn @ V per (b,h) -> g_C [b,n,h*64+d]. grid (8 it, 96 bh)
// ---------------------------------------------------------------------------
__global__ __launch_bounds__(256, 2) void k_av() {
    __shared__ float As[128 * 20];
    __shared__ float Bs[16 * 68];
    const int tid = threadIdx.x;
    const int it = blockIdx.x, bh = blockIdx.y;
    const int b = bh / 12, h = bh % 12;
    const float* Apm = g_S + (size_t)bh * Nn * Nn + (size_t)it * 128 * 1024;
    const float* Vp  = g_V + (size_t)bh * Nn * 64;

    const int tx4 = (tid & 15) * 4, ty4 = (tid >> 4) * 4;
    const int ar = tid >> 2, ak4 = (tid & 3) * 4;
    const int bk = tid >> 4, bn4 = (tid & 15) * 4;
    const float* Ap = Apm + (size_t)ar * 1024 + ak4;

    ull acc[8][2];
    #pragma unroll
    for (int m = 0; m < 8; ++m) { acc[m][0] = 0ull; acc[m][1] = 0ull; }

    float4 ra0 = *(const float4*)(Ap);
    float4 ra1 = *(const float4*)(Ap + (size_t)64 * 1024);
    float4 rb0 = *(const float4*)(Vp + (size_t)bk * 64 + bn4);

    for (int kt = 0; kt < 64; ++kt) {
        *(float4*)&As[ar * 20 + ak4]        = ra0;
        *(float4*)&As[(ar + 64) * 20 + ak4] = ra1;
        *(float4*)&Bs[bk * 68 + bn4]        = rb0;
        __syncthreads();
        if (kt < 63) {
            ra0 = *(const float4*)(Ap + (kt + 1) * 16);
            ra1 = *(const float4*)(Ap + (size_t)64 * 1024 + (kt + 1) * 16);
            rb0 = *(const float4*)(Vp + (size_t)((kt + 1) * 16 + bk) * 64 + bn4);
        }
        mma16_nn64(As, Bs, ty4, tx4, acc);
        __syncthreads();
    }

    #pragma unroll
    for (int half = 0; half < 2; ++half)
        #pragma unroll
        for (int i = 0; i < 4; ++i) {
            const int m = it * 128 + half * 64 + ty4 + i;
            F4U2 v;
            v.u.lo = acc[half * 4 + i][0];
            v.u.hi = acc[half * 4 + i][1];
            *(float4*)(g_C + ((size_t)b * 1024 + m) * 768 + h * 64 + tx4) = v.f;
        }
}

// ---------------------------------------------------------------------------
// K5: out = Ctx @ Wo + bo. grid (6 bx, 64 by)
// ---------------------------------------------------------------------------
__global__ __launch_bounds__(256, 2) void k_out(const float* __restrict__ Wo,
                                                const float* __restrict__ bo,
                                                float* __restrict__ out) {
    __shared__ float As[128 * 20];
    __shared__ float Bs[16 * 132];
    const int tid = threadIdx.x;
    const int bx = blockIdx.x, by = blockIdx.y;
    const float* Bp = Wo + bx * 128;

    const int tx4 = (tid & 15) * 4, ty4 = (tid >> 4) * 4;
    const int ar = tid >> 2, ak4 = (tid & 3) * 4;
    const int bk = tid >> 4, bn4 = (tid & 15) * 4;
    const float* Ap = g_C + ((size_t)by * 128 + ar) * 768 + ak4;

    ull acc[8][4];
    #pragma unroll
    for (int m = 0; m < 8; ++m)
        #pragma unroll
        for (int n = 0; n < 4; ++n) acc[m][n] = 0ull;

    float4 ra0 = *(const float4*)(Ap);
    float4 ra1 = *(const float4*)(Ap + (size_t)64 * 768);
    float4 rb0 = *(const float4*)(Bp + (size_t)bk * 768 + bn4);
    float4 rb1 = *(const float4*)(Bp + (size_t)bk * 768 + bn4 + 64);

    for (int kt = 0; kt < 48; ++kt) {
        *(float4*)&As[ar * 20 + ak4]        = ra0;
        *(float4*)&As[(ar + 64) * 20 + ak4] = ra1;
        *(float4*)&Bs[bk * 132 + bn4]       = rb0;
        *(float4*)&Bs[bk * 132 + bn4 + 64]  = rb1;
        __syncthreads();
        if (kt < 47) {
            ra0 = *(const float4*)(Ap + (kt + 1) * 16);
            ra1 = *(const float4*)(Ap + (size_t)64 * 768 + (kt + 1) * 16);
            rb0 = *(const float4*)(Bp + (size_t)((kt + 1) * 16 + bk) * 768 + bn4);
            rb1 = *(const float4*)(Bp + (size_t)((kt + 1) * 16 + bk) * 768 + bn4 + 64);
        }
        mma16_nn128(As, Bs, ty4, tx4, acc);
        __syncthreads();
    }

    float4 bias0 = *(const float4*)(bo + bx * 128 + tx4);
    float4 bias1 = *(const float4*)(bo + bx * 128 + 64 + tx4);
    #pragma unroll
    for (int half = 0; half < 2; ++half)
        #pragma unroll
        for (int i = 0; i < 4; ++i) {
            const int m = by * 128 + half * 64 + ty4 + i;
            #pragma unroll
            for (int g = 0; g < 2; ++g) {
                F4U2 v;
                v.u.lo = acc[half * 4 + i][g * 2];
                v.u.hi = acc[half * 4 + i][g * 2 + 1];
                float4 bias = g ? bias1 : bias0;
                v.f.x += bias.x; v.f.y += bias.y; v.f.z += bias.z; v.f.w += bias.w;
                *(float4*)(out + (size_t)m * 768 + bx * 128 + g * 64 + tx4) = v.f;
            }
        }
}

// ---------------------------------------------------------------------------
extern "C" void kernel_launch(void* const* d_in, const int* in_sizes, int n_in,
                              void* d_out, int out_size) {
    const float* x     = (const float*)d_in[0];
    const float* Wq    = (const float*)d_in[1];
    const float* Wkv   = (const float*)d_in[2];
    const float* mpre  = (const float*)d_in[3];
    const float* mpost = (const float*)d_in[4];
    const float* Wo    = (const float*)d_in[5];
    const float* bo    = (const float*)d_in[6];
    float* out = (float*)d_out;

    k_qkv    <<<dim3(18, 64),    256>>>(x, Wq, Wkv);
    k_dots   <<<dim3(8, 8, 96),  256>>>();
    k_mixsoft<<<8192,            256>>>(mpre, mpost);
    k_av     <<<dim3(8, 96),     256>>>();
    k_out    <<<dim3(6, 64),     256>>>(Wo, bo, out);
}

// round 3
// speedup vs baseline: 1.8677x; 1.8677x over previous
#include <cuda_runtime.h>
#include <math.h>

#define Bb 8
#define Nn 1024
#define Hh 12

// Scratch (static device globals)
__device__ float g_Q[(size_t)Bb*Hh*Nn*64];
__device__ float g_K[(size_t)Bb*Hh*Nn*64];
__device__ float g_V[(size_t)Bb*Hh*Nn*64];
__device__ float g_S[(size_t)Bb*Hh*Nn*Nn];
__device__ float g_C[(size_t)Bb*Nn*768];

// ---------------------------------------------------------------------------
// tf32 split helpers: x = hi + lo, both tf32-rounded. hi*hi + hi*lo + lo*hi
// reproduces fp32 products to ~2^-22 relative.
// ---------------------------------------------------------------------------
__device__ __forceinline__ void split1(float x, unsigned &h, unsigned &l) {
    asm("cvt.rna.tf32.f32 %0, %1;" : "=r"(h) : "f"(x));
    float r = x - __uint_as_float(h);
    asm("cvt.rna.tf32.f32 %0, %1;" : "=r"(l) : "f"(r));
}
__device__ __forceinline__ void split4(float4 v, uint4 &h, uint4 &l) {
    split1(v.x, h.x, l.x); split1(v.y, h.y, l.y);
    split1(v.z, h.z, l.z); split1(v.w, h.w, l.w);
}

#define MMA4(c, a, b) \
  asm("mma.sync.aligned.m16n8k8.row.col.f32.tf32.tf32.f32 " \
      "{%0,%1,%2,%3}, {%4,%5,%6,%7}, {%8,%9}, {%0,%1,%2,%3};" \
      : "+f"(c[0]), "+f"(c[1]), "+f"(c[2]), "+f"(c[3]) \
      : "r"(a[0]), "r"(a[1]), "r"(a[2]), "r"(a[3]), "r"(b[0]), "r"(b[1]))

// ---------------------------------------------------------------------------
// Compute cores. As: hi[128][20] then lo[128][20] (k-chunk 16, pitch 20).
// mma_chunk_bn: Bs = hi[16][BP] then lo[16][BP]  (B as [k][n])
// mma_chunk_bt: Bs = hi[128][20] then lo[128][20] (B as [n][k])
// Warp tile: MT*16 rows x NT*8 cols.
// ---------------------------------------------------------------------------
template<int MT, int NT, int BP>
__device__ __forceinline__ void mma_chunk_bn(const unsigned* __restrict__ As,
                                             const unsigned* __restrict__ Bs,
                                             int wm, int wn, int lane,
                                             float acc[MT][NT][4]) {
    const int g = lane >> 2, th = lane & 3;
    const unsigned* Alo = As + 128 * 20;
    const unsigned* Blo = Bs + 16 * BP;
    #pragma unroll
    for (int kk = 0; kk < 16; kk += 8) {
        unsigned a[MT][4], bh[NT][2], bl[NT][2];
        #pragma unroll
        for (int mt = 0; mt < MT; ++mt) {
            int r = (wm + mt * 16 + g) * 20 + kk + th;
            a[mt][0] = As[r];       a[mt][1] = As[r + 160];
            a[mt][2] = As[r + 4];   a[mt][3] = As[r + 164];
        }
        #pragma unroll
        for (int nt = 0; nt < NT; ++nt) {
            int c = (kk + th) * BP + wn + nt * 8 + g;
            bh[nt][0] = Bs[c];  bh[nt][1] = Bs[c + 4 * BP];
            bl[nt][0] = Blo[c]; bl[nt][1] = Blo[c + 4 * BP];
        }
        #pragma unroll
        for (int mt = 0; mt < MT; ++mt)
            #pragma unroll
            for (int nt = 0; nt < NT; ++nt) {
                MMA4(acc[mt][nt], a[mt], bh[nt]);
                MMA4(acc[mt][nt], a[mt], bl[nt]);
            }
        #pragma unroll
        for (int mt = 0; mt < MT; ++mt) {
            int r = (wm + mt * 16 + g) * 20 + kk + th;
            a[mt][0] = Alo[r];     a[mt][1] = Alo[r + 160];
            a[mt][2] = Alo[r + 4]; a[mt][3] = Alo[r + 164];
        }
        #pragma unroll
        for (int mt = 0; mt < MT; ++mt)
            #pragma unroll
            for (int nt = 0; nt < NT; ++nt)
                MMA4(acc[mt][nt], a[mt], bh[nt]);
    }
}

template<int MT, int NT>
__device__ __forceinline__ void mma_chunk_bt(const unsigned* __restrict__ As,
                                             const unsigned* __restrict__ Bs,
                                             int wm, int wn, int lane,
                                             float acc[MT][NT][4]) {
    const int g = lane >> 2, th = lane & 3;
    const unsigned* Alo = As + 128 * 20;
    const unsigned* Blo = Bs + 128 * 20;
    #pragma unroll
    for (int kk = 0; kk < 16; kk += 8) {
        unsigned a[MT][4], bh[NT][2], bl[NT][2];
        #pragma unroll
        for (int mt = 0; mt < MT; ++mt) {
            int r = (wm + mt * 16 + g) * 20 + kk + th;
            a[mt][0] = As[r];       a[mt][1] = As[r + 160];
            a[mt][2] = As[r + 4];   a[mt][3] = As[r + 164];
        }
        #pragma unroll
        for (int nt = 0; nt < NT; ++nt) {
            int c = (wn + nt * 8 + g) * 20 + kk + th;
            bh[nt][0] = Bs[c];  bh[nt][1] = Bs[c + 4];
            bl[nt][0] = Blo[c]; bl[nt][1] = Blo[c + 4];
        }
        #pragma unroll
        for (int mt = 0; mt < MT; ++mt)
            #pragma unroll
            for (int nt = 0; nt < NT; ++nt) {
                MMA4(acc[mt][nt], a[mt], bh[nt]);
                MMA4(acc[mt][nt], a[mt], bl[nt]);
            }
        #pragma unroll
        for (int mt = 0; mt < MT; ++mt) {
            int r = (wm + mt * 16 + g) * 20 + kk + th;
            a[mt][0] = Alo[r];     a[mt][1] = Alo[r + 160];
            a[mt][2] = Alo[r + 4]; a[mt][3] = Alo[r + 164];
        }
        #pragma unroll
        for (int mt = 0; mt < MT; ++mt)
            #pragma unroll
            for (int nt = 0; nt < NT; ++nt)
                MMA4(acc[mt][nt], a[mt], bh[nt]);
    }
}

// ---------------------------------------------------------------------------
// K1: QKV projection. x[8192,768] @ [Wq|Wkv] -> g_Q/g_K/g_V. grid (18, 64)
// ---------------------------------------------------------------------------
__global__ __launch_bounds__(256) void k_qkv(const float* __restrict__ x,
                                             const float* __restrict__ Wq,
                                             const float* __restrict__ Wkv) {
    __shared__ unsigned As[2 * 128 * 20];
    __shared__ unsigned Bs[2 * 16 * 136];
    const int tid = threadIdx.x, lane = tid & 31, w = tid >> 5;
    const int bx = blockIdx.x, by = blockIdx.y;
    const int nglob = bx * 128;
    const float* Bp = (nglob < 768) ? (Wq + nglob) : (Wkv + (nglob - 768));
    const int ldb = (nglob < 768) ? 768 : 1536;
    const int wm = (w >> 2) * 64, wn = (w & 3) * 32;

    const int ar = tid >> 2, ak4 = (tid & 3) * 4;
    const int bk = tid >> 4, bn4 = (tid & 15) * 4;
    const float* Ap = x + ((size_t)by * 128 + ar) * 768 + ak4;

    float acc[4][4][4] = {};

    float4 ra0 = *(const float4*)(Ap);
    float4 ra1 = *(const float4*)(Ap + (size_t)64 * 768);
    float4 rb0 = *(const float4*)(Bp + (size_t)bk * ldb + bn4);
    float4 rb1 = *(const float4*)(Bp + (size_t)bk * ldb + bn4 + 64);

    for (int kt = 0; kt < 48; ++kt) {
        uint4 h, l;
        split4(ra0, h, l);
        *(uint4*)&As[ar * 20 + ak4] = h; *(uint4*)&As[2560 + ar * 20 + ak4] = l;
        split4(ra1, h, l);
        *(uint4*)&As[(ar + 64) * 20 + ak4] = h; *(uint4*)&As[2560 + (ar + 64) * 20 + ak4] = l;
        split4(rb0, h, l);
        *(uint4*)&Bs[bk * 136 + bn4] = h; *(uint4*)&Bs[2176 + bk * 136 + bn4] = l;
        split4(rb1, h, l);
        *(uint4*)&Bs[bk * 136 + bn4 + 64] = h; *(uint4*)&Bs[2176 + bk * 136 + bn4 + 64] = l;
        __syncthreads();
        if (kt < 47) {
            ra0 = *(const float4*)(Ap + (kt + 1) * 16);
            ra1 = *(const float4*)(Ap + (size_t)64 * 768 + (kt + 1) * 16);
            rb0 = *(const float4*)(Bp + (size_t)((kt + 1) * 16 + bk) * ldb + bn4);
            rb1 = *(const float4*)(Bp + (size_t)((kt + 1) * 16 + bk) * ldb + bn4 + 64);
        }
        mma_chunk_bn<4, 4, 136>(As, Bs, wm, wn, lane, acc);
        __syncthreads();
    }

    const int g = lane >> 2, th = lane & 3;
    #pragma unroll
    for (int nt = 0; nt < 4; ++nt) {
        const int col = nglob + wn + nt * 8 + 2 * th;
        const int mat = col / 768;
        const int within = col - mat * 768;
        const int head = within >> 6, d = within & 63;
        float* G = (mat == 0) ? g_Q : (mat == 1) ? g_K : g_V;
        #pragma unroll
        for (int mt = 0; mt < 4; ++mt) {
            const int m0 = by * 128 + wm + mt * 16 + g;
            const int b = m0 >> 10, nr = m0 & 1023;
            float* p = G + (((size_t)b * 12 + head) * 1024 + nr) * 64 + d;
            *(float2*)p = make_float2(acc[mt][nt][0], acc[mt][nt][1]);
            *(float2*)(p + 8 * 64) = make_float2(acc[mt][nt][2], acc[mt][nt][3]);
        }
    }
}

// ---------------------------------------------------------------------------
// K2: dots = scale * Q @ K^T per (b,h). grid (8 jt, 8 it, 96 bh)
// ---------------------------------------------------------------------------
__global__ __launch_bounds__(256) void k_dots() {
    __shared__ unsigned As[2 * 128 * 20];
    __shared__ unsigned Bs[2 * 128 * 20];
    const int tid = threadIdx.x, lane = tid & 31, w = tid >> 5;
    const int jt = blockIdx.x, it = blockIdx.y, bh = blockIdx.z;
    const float* Qp = g_Q + (size_t)bh * Nn * 64;
    const float* Kp = g_K + (size_t)bh * Nn * 64;
    float* Sp = g_S + (size_t)bh * Nn * Nn;
    const int wm = (w >> 2) * 64, wn = (w & 3) * 32;

    const int ar = tid >> 2, ak4 = (tid & 3) * 4;
    const float* Ap = Qp + ((size_t)it * 128 + ar) * 64 + ak4;
    const float* Bp = Kp + ((size_t)jt * 128 + ar) * 64 + ak4;

    float acc[4][4][4] = {};

    float4 ra0 = *(const float4*)(Ap);
    float4 ra1 = *(const float4*)(Ap + 64 * 64);
    float4 rb0 = *(const float4*)(Bp);
    float4 rb1 = *(const float4*)(Bp + 64 * 64);

    for (int kt = 0; kt < 4; ++kt) {
        uint4 h, l;
        split4(ra0, h, l);
        *(uint4*)&As[ar * 20 + ak4] = h; *(uint4*)&As[2560 + ar * 20 + ak4] = l;
        split4(ra1, h, l);
        *(uint4*)&As[(ar + 64) * 20 + ak4] = h; *(uint4*)&As[2560 + (ar + 64) * 20 + ak4] = l;
        split4(rb0, h, l);
        *(uint4*)&Bs[ar * 20 + ak4] = h; *(uint4*)&Bs[2560 + ar * 20 + ak4] = l;
        split4(rb1, h, l);
        *(uint4*)&Bs[(ar + 64) * 20 + ak4] = h; *(uint4*)&Bs[2560 + (ar + 64) * 20 + ak4] = l;
        __syncthreads();
        if (kt < 3) {
            ra0 = *(const float4*)(Ap + (kt + 1) * 16);
            ra1 = *(const float4*)(Ap + 64 * 64 + (kt + 1) * 16);
            rb0 = *(const float4*)(Bp + (kt + 1) * 16);
            rb1 = *(const float4*)(Bp + 64 * 64 + (kt + 1) * 16);
        }
        mma_chunk_bt<4, 4>(As, Bs, wm, wn, lane, acc);
        __syncthreads();
    }

    const int g = lane >> 2, th = lane & 3;
    const float s = 0.125f;
    #pragma unroll
    for (int mt = 0; mt < 4; ++mt) {
        const int m = it * 128 + wm + mt * 16 + g;
        #pragma unroll
        for (int nt = 0; nt < 4; ++nt) {
            const int c = jt * 128 + wn + nt * 8 + 2 * th;
            *(float2*)(Sp + (size_t)m * 1024 + c) =
                make_float2(acc[mt][nt][0] * s, acc[mt][nt][1] * s);
            *(float2*)(Sp + (size_t)(m + 8) * 1024 + c) =
                make_float2(acc[mt][nt][2] * s, acc[mt][nt][3] * s);
        }
    }
}

// ---------------------------------------------------------------------------
// K3: mix_pre -> softmax -> mix_post, fused, in-place on g_S. (unchanged)
// ---------------------------------------------------------------------------
__global__ __launch_bounds__(256) void k_mixsoft(const float* __restrict__ mix_pre,
                                                 const float* __restrict__ mix_post) {
    __shared__ float raw[12 * 512];
    __shared__ float pre[144], post[144];
    __shared__ float wred[96];
    __shared__ float gstat[24];
    const int t = threadIdx.x;
    const int b = blockIdx.x >> 10, i = blockIdx.x & 1023;
    if (t < 144) { pre[t] = mix_pre[t]; post[t] = mix_post[t]; }
    const size_t rowbase = (size_t)b * 12 * 1048576 + (size_t)i * 1024;

    float mx[12][4];
    #pragma unroll
    for (int g = 0; g < 12; ++g)
        mx[g][0] = mx[g][1] = mx[g][2] = mx[g][3] = 0.f;

    #pragma unroll
    for (int c = 0; c < 2; ++c) {
        __syncthreads();
        #pragma unroll
        for (int u = 0; u < 24; ++u) {
            int idx = u * 256 + t;
            int h = idx >> 9, j = idx & 511;
            raw[idx] = g_S[rowbase + (size_t)h * 1048576 + c * 512 + j];
        }
        __syncthreads();
        float rv[12][2];
        #pragma unroll
        for (int h = 0; h < 12; ++h) {
            rv[h][0] = raw[h * 512 + t];
            rv[h][1] = raw[h * 512 + t + 256];
        }
        #pragma unroll
        for (int g = 0; g < 12; ++g) {
            float a0 = mx[g][c * 2], a1 = mx[g][c * 2 + 1];
            #pragma unroll
            for (int h = 0; h < 12; ++h) {
                float p = pre[h * 12 + g];
                a0 += rv[h][0] * p;
                a1 += rv[h][1] * p;
            }
            mx[g][c * 2] = a0; mx[g][c * 2 + 1] = a1;
        }
    }

    const int lane = t & 31, wid = t >> 5;
    #pragma unroll
    for (int g = 0; g < 12; ++g) {
        float m = fmaxf(fmaxf(mx[g][0], mx[g][1]), fmaxf(mx[g][2], mx[g][3]));
        #pragma unroll
        for (int o = 16; o > 0; o >>= 1) m = fmaxf(m, __shfl_xor_sync(0xffffffffu, m, o));
        if (lane == 0) wred[g * 8 + wid] = m;
    }
    __syncthreads();
    if (t < 12) {
        float m = wred[t * 8];
        #pragma unroll
        for (int w2 = 1; w2 < 8; ++w2) m = fmaxf(m, wred[t * 8 + w2]);
        gstat[t] = m;
    }
    __syncthreads();
    #pragma unroll
    for (int g = 0; g < 12; ++g) {
        float mg = gstat[g];
        float s = 0.f;
        #pragma unroll
        for (int r = 0; r < 4; ++r) { mx[g][r] = __expf(mx[g][r] - mg); s += mx[g][r]; }
        #pragma unroll
        for (int o = 16; o > 0; o >>= 1) s += __shfl_xor_sync(0xffffffffu, s, o);
        if (lane == 0) wred[g * 8 + wid] = s;
    }
    __syncthreads();
    if (t < 12) {
        float s = 0.f;
        #pragma unroll
        for (int w2 = 0; w2 < 8; ++w2) s += wred[t * 8 + w2];
        gstat[12 + t] = 1.0f / s;
    }
    __syncthreads();
    #pragma unroll
    for (int g = 0; g < 12; ++g) {
        float inv = gstat[12 + g];
        #pragma unroll
        for (int r = 0; r < 4; ++r) mx[g][r] *= inv;
    }
    #pragma unroll
    for (int h = 0; h < 12; ++h) {
        float o0 = 0.f, o1 = 0.f, o2 = 0.f, o3 = 0.f;
        #pragma unroll
        for (int g = 0; g < 12; ++g) {
            float p = post[g * 12 + h];
            o0 += mx[g][0] * p; o1 += mx[g][1] * p;
            o2 += mx[g][2] * p; o3 += mx[g][3] * p;
        }
        float* dst = g_S + rowbase + (size_t)h * 1048576;
        dst[t]       = o0; dst[t + 256] = o1;
        dst[t + 512] = o2; dst[t + 768] = o3;
    }
}

// ---------------------------------------------------------------------------
// K4: O = attn @ V per (b,h) -> g_C [b,n,h*64+d]. grid (8 it, 96 bh)
// ---------------------------------------------------------------------------
__global__ __launch_bounds__(256) void k_av() {
    __shared__ unsigned As[2 * 128 * 20];
    __shared__ unsigned Bs[2 * 16 * 72];
    const int tid = threadIdx.x, lane = tid & 31, w = tid >> 5;
    const int it = blockIdx.x, bh = blockIdx.y;
    const int b = bh / 12, h = bh % 12;
    const float* Apm = g_S + (size_t)bh * Nn * Nn + (size_t)it * 128 * 1024;
    const float* Vp  = g_V + (size_t)bh * Nn * 64;
    const int wm = (w >> 1) * 32, wn = (w & 1) * 32;

    const int ar = tid >> 2, ak4 = (tid & 3) * 4;
    const int bk = tid >> 4, bn4 = (tid & 15) * 4;
    const float* Ap = Apm + (size_t)ar * 1024 + ak4;

    float acc[2][4][4] = {};

    float4 ra0 = *(const float4*)(Ap);
    float4 ra1 = *(const float4*)(Ap + (size_t)64 * 1024);
    float4 rb0 = *(const float4*)(Vp + (size_t)bk * 64 + bn4);

    for (int kt = 0; kt < 64; ++kt) {
        uint4 hh, ll;
        split4(ra0, hh, ll);
        *(uint4*)&As[ar * 20 + ak4] = hh; *(uint4*)&As[2560 + ar * 20 + ak4] = ll;
        split4(ra1, hh, ll);
        *(uint4*)&As[(ar + 64) * 20 + ak4] = hh; *(uint4*)&As[2560 + (ar + 64) * 20 + ak4] = ll;
        split4(rb0, hh, ll);
        *(uint4*)&Bs[bk * 72 + bn4] = hh; *(uint4*)&Bs[1152 + bk * 72 + bn4] = ll;
        __syncthreads();
        if (kt < 63) {
            ra0 = *(const float4*)(Ap + (kt + 1) * 16);
            ra1 = *(const float4*)(Ap + (size_t)64 * 1024 + (kt + 1) * 16);
            rb0 = *(const float4*)(Vp + (size_t)((kt + 1) * 16 + bk) * 64 + bn4);
        }
        mma_chunk_bn<2, 4, 72>(As, Bs, wm, wn, lane, acc);
        __syncthreads();
    }

    const int g = lane >> 2, th = lane & 3;
    #pragma unroll
    for (int mt = 0; mt < 2; ++mt) {
        const int m = it * 128 + wm + mt * 16 + g;
        #pragma unroll
        for (int nt = 0; nt < 4; ++nt) {
            const int c = wn + nt * 8 + 2 * th;
            float* p = g_C + ((size_t)b * 1024 + m) * 768 + h * 64 + c;
            *(float2*)p = make_float2(acc[mt][nt][0], acc[mt][nt][1]);
            *(float2*)(p + (size_t)8 * 768) = make_float2(acc[mt][nt][2], acc[mt][nt][3]);
        }
    }
}

// ---------------------------------------------------------------------------
// K5: out = Ctx @ Wo + bo. grid (6, 64)
// ---------------------------------------------------------------------------
__global__ __launch_bounds__(256) void k_out(const float* __restrict__ Wo,
                                             const float* __restrict__ bo,
                                             float* __restrict__ out) {
    __shared__ unsigned As[2 * 128 * 20];
    __shared__ unsigned Bs[2 * 16 * 136];
    const int tid = threadIdx.x, lane = tid & 31, w = tid >> 5;
    const int bx = blockIdx.x, by = blockIdx.y;
    const float* Bp = Wo + bx * 128;
    const int wm = (w >> 2) * 64, wn = (w & 3) * 32;

    const int ar = tid >> 2, ak4 = (tid & 3) * 4;
    const int bk = tid >> 4, bn4 = (tid & 15) * 4;
    const float* Ap = g_C + ((size_t)by * 128 + ar) * 768 + ak4;

    float acc[4][4][4] = {};

    float4 ra0 = *(const float4*)(Ap);
    float4 ra1 = *(const float4*)(Ap + (size_t)64 * 768);
    float4 rb0 = *(const float4*)(Bp + (size_t)bk * 768 + bn4);
    float4 rb1 = *(const float4*)(Bp + (size_t)bk * 768 + bn4 + 64);

    for (int kt = 0; kt < 48; ++kt) {
        uint4 h, l;
        split4(ra0, h, l);
        *(uint4*)&As[ar * 20 + ak4] = h; *(uint4*)&As[2560 + ar * 20 + ak4] = l;
        split4(ra1, h, l);
        *(uint4*)&As[(ar + 64) * 20 + ak4] = h; *(uint4*)&As[2560 + (ar + 64) * 20 + ak4] = l;
        split4(rb0, h, l);
        *(uint4*)&Bs[bk * 136 + bn4] = h; *(uint4*)&Bs[2176 + bk * 136 + bn4] = l;
        split4(rb1, h, l);
        *(uint4*)&Bs[bk * 136 + bn4 + 64] = h; *(uint4*)&Bs[2176 + bk * 136 + bn4 + 64] = l;
        __syncthreads();
        if (kt < 47) {
            ra0 = *(const float4*)(Ap + (kt + 1) * 16);
            ra1 = *(const float4*)(Ap + (size_t)64 * 768 + (kt + 1) * 16);
            rb0 = *(const float4*)(Bp + (size_t)((kt + 1) * 16 + bk) * 768 + bn4);
            rb1 = *(const float4*)(Bp + (size_t)((kt + 1) * 16 + bk) * 768 + bn4 + 64);
        }
        mma_chunk_bn<4, 4, 136>(As, Bs, wm, wn, lane, acc);
        __syncthreads();
    }

    const int g = lane >> 2, th = lane & 3;
    #pragma unroll
    for (int nt = 0; nt < 4; ++nt) {
        const int c = bx * 128 + wn + nt * 8 + 2 * th;
        const float b0v = bo[c], b1v = bo[c + 1];
        #pragma unroll
        for (int mt = 0; mt < 4; ++mt) {
            const int m = by * 128 + wm + mt * 16 + g;
            *(float2*)(out + (size_t)m * 768 + c) =
                make_float2(acc[mt][nt][0] + b0v, acc[mt][nt][1] + b1v);
            *(float2*)(out + (size_t)(m + 8) * 768 + c) =
                make_float2(acc[mt][nt][2] + b0v, acc[mt][nt][3] + b1v);
        }
    }
}

// ---------------------------------------------------------------------------
extern "C" void kernel_launch(void* const* d_in, const int* in_sizes, int n_in,
                              void* d_out, int out_size) {
    const float* x     = (const float*)d_in[0];
    const float* Wq    = (const float*)d_in[1];
    const float* Wkv   = (const float*)d_in[2];
    const float* mpre  = (const float*)d_in[3];
    const float* mpost = (const float*)d_in[4];
    const float* Wo    = (const float*)d_in[5];
    const float* bo    = (const float*)d_in[6];
    float* out = (float*)d_out;

    k_qkv    <<<dim3(18, 64),   256>>>(x, Wq, Wkv);
    k_dots   <<<dim3(8, 8, 96), 256>>>();
    k_mixsoft<<<8192,           256>>>(mpre, mpost);
    k_av     <<<dim3(8, 96),    256>>>();
    k_out    <<<dim3(6, 64),    256>>>(Wo, bo, out);
}

// round 4
// speedup vs baseline: 3.0525x; 1.6344x over previous
#include <cuda_runtime.h>
#include <cuda_fp16.h>
#include <math.h>

#define Bb 8
#define Nn 1024
#define Hh 12

// Scratch (static device globals)
__device__ float g_Q[(size_t)Bb*Hh*Nn*64];
__device__ float g_K[(size_t)Bb*Hh*Nn*64];
__device__ float g_V[(size_t)Bb*Hh*Nn*64];
__device__ float g_S[(size_t)Bb*Hh*Nn*Nn];
__device__ float g_C[(size_t)Bb*Nn*768];

// ---------------------------------------------------------------------------
// fp16 split: x = hi + lo (both fp16). hi*hi + hi*lo + lo*hi ~ fp32 product
// to ~2^-21 relative.
// ---------------------------------------------------------------------------
__device__ __forceinline__ void split2(float a, float b, unsigned &h, unsigned &l) {
    __half ha = __float2half_rn(a), hb = __float2half_rn(b);
    __half2 H = __halves2half2(ha, hb);
    __half2 L = __halves2half2(__float2half_rn(a - __half2float(ha)),
                               __float2half_rn(b - __half2float(hb)));
    h = *(unsigned*)&H; l = *(unsigned*)&L;
}
__device__ __forceinline__ void split4(float4 v, uint2 &h, uint2 &l) {
    split2(v.x, v.y, h.x, l.x); split2(v.z, v.w, h.y, l.y);
}

#define LDSM_X4(r0, r1, r2, r3, a) \
  asm volatile("ldmatrix.sync.aligned.m8n8.x4.shared.b16 {%0,%1,%2,%3},[%4];" \
               : "=r"(r0), "=r"(r1), "=r"(r2), "=r"(r3) : "r"(a))
#define LDSM_X4T(r0, r1, r2, r3, a) \
  asm volatile("ldmatrix.sync.aligned.m8n8.x4.trans.shared.b16 {%0,%1,%2,%3},[%4];" \
               : "=r"(r0), "=r"(r1), "=r"(r2), "=r"(r3) : "r"(a))
#define MMA16(c, a, b) \
  asm volatile("mma.sync.aligned.m16n8k16.row.col.f32.f16.f16.f32 " \
               "{%0,%1,%2,%3},{%4,%5,%6,%7},{%8,%9},{%0,%1,%2,%3};" \
               : "+f"(c[0]), "+f"(c[1]), "+f"(c[2]), "+f"(c[3]) \
               : "r"(a[0]), "r"(a[1]), "r"(a[2]), "r"(a[3]), "r"(b[0]), "r"(b[1]))

// ---------------------------------------------------------------------------
// K1: QKV projection. x[8192,768] @ [Wq|Wkv] -> g_Q/g_K/g_V. grid (18, 64)
// As: [128][24] halfs (hi), +[128][24] lo.  Bs: [16][136] halfs hi, + lo.
// ---------------------------------------------------------------------------
__global__ __launch_bounds__(256, 2) void k_qkv(const float* __restrict__ x,
                                                const float* __restrict__ Wq,
                                                const float* __restrict__ Wkv) {
    __shared__ __half As[2 * 128 * 24];
    __shared__ __half Bs[2 * 16 * 136];
    const int tid = threadIdx.x, lane = tid & 31, w = tid >> 5;
    const int bx = blockIdx.x, by = blockIdx.y;
    const int nglob = bx * 128;
    const float* Bp = (nglob < 768) ? (Wq + nglob) : (Wkv + (nglob - 768));
    const int ldb = (nglob < 768) ? 768 : 1536;
    const int wm = (w >> 2) * 64, wn = (w & 3) * 32;

    const int ar = tid >> 2, ak4 = (tid & 3) * 4;
    const int bk = tid >> 4, bn4 = (tid & 15) * 4;
    const float* Ap = x + ((size_t)by * 128 + ar) * 768 + ak4;

    const int lr = lane & 7, hs = (lane >> 3) & 1, kc = lane >> 4;
    const unsigned sa = (unsigned)__cvta_generic_to_shared(As);
    const unsigned sb = (unsigned)__cvta_generic_to_shared(Bs);
    const unsigned aaddr = sa + ((wm + hs * 8 + lr) * 24 + kc * 8) * 2;
    const unsigned baddr = sb + ((hs * 8 + lr) * 136 + wn + kc * 8) * 2;
    const unsigned ALO = 128 * 24 * 2, BLO = 16 * 136 * 2;

    float acc[4][4][4] = {};

    float4 ra0 = *(const float4*)(Ap);
    float4 ra1 = *(const float4*)(Ap + (size_t)64 * 768);
    float4 rb0 = *(const float4*)(Bp + (size_t)bk * ldb + bn4);
    float4 rb1 = *(const float4*)(Bp + (size_t)bk * ldb + bn4 + 64);

    for (int kt = 0; kt < 48; ++kt) {
        uint2 h, l;
        split4(ra0, h, l);
        *(uint2*)&As[ar * 24 + ak4] = h;            *(uint2*)&As[3072 + ar * 24 + ak4] = l;
        split4(ra1, h, l);
        *(uint2*)&As[(ar + 64) * 24 + ak4] = h;     *(uint2*)&As[3072 + (ar + 64) * 24 + ak4] = l;
        split4(rb0, h, l);
        *(uint2*)&Bs[bk * 136 + bn4] = h;           *(uint2*)&Bs[2176 + bk * 136 + bn4] = l;
        split4(rb1, h, l);
        *(uint2*)&Bs[bk * 136 + bn4 + 64] = h;      *(uint2*)&Bs[2176 + bk * 136 + bn4 + 64] = l;
        __syncthreads();
        if (kt < 47) {
            ra0 = *(const float4*)(Ap + (kt + 1) * 16);
            ra1 = *(const float4*)(Ap + (size_t)64 * 768 + (kt + 1) * 16);
            rb0 = *(const float4*)(Bp + (size_t)((kt + 1) * 16 + bk) * ldb + bn4);
            rb1 = *(const float4*)(Bp + (size_t)((kt + 1) * 16 + bk) * ldb + bn4 + 64);
        }
        unsigned af[4][4], bh[4][2], bl[4][2];
        #pragma unroll
        for (int mt = 0; mt < 4; ++mt)
            LDSM_X4(af[mt][0], af[mt][1], af[mt][2], af[mt][3], aaddr + mt * 768);
        #pragma unroll
        for (int n2 = 0; n2 < 2; ++n2) {
            LDSM_X4T(bh[2*n2][0], bh[2*n2][1], bh[2*n2+1][0], bh[2*n2+1][1], baddr + n2 * 32);
            LDSM_X4T(bl[2*n2][0], bl[2*n2][1], bl[2*n2+1][0], bl[2*n2+1][1], baddr + n2 * 32 + BLO);
        }
        #pragma unroll
        for (int mt = 0; mt < 4; ++mt)
            #pragma unroll
            for (int nt = 0; nt < 4; ++nt) {
                MMA16(acc[mt][nt], af[mt], bh[nt]);
                MMA16(acc[mt][nt], af[mt], bl[nt]);
            }
        #pragma unroll
        for (int mt = 0; mt < 4; ++mt)
            LDSM_X4(af[mt][0], af[mt][1], af[mt][2], af[mt][3], aaddr + mt * 768 + ALO);
        #pragma unroll
        for (int mt = 0; mt < 4; ++mt)
            #pragma unroll
            for (int nt = 0; nt < 4; ++nt)
                MMA16(acc[mt][nt], af[mt], bh[nt]);
        __syncthreads();
    }

    const int g = lane >> 2, th = lane & 3;
    #pragma unroll
    for (int nt = 0; nt < 4; ++nt) {
        const int col = nglob + wn + nt * 8 + 2 * th;
        const int mat = col / 768;
        const int within = col - mat * 768;
        const int head = within >> 6, d = within & 63;
        float* G = (mat == 0) ? g_Q : (mat == 1) ? g_K : g_V;
        #pragma unroll
        for (int mt = 0; mt < 4; ++mt) {
            const int m0 = by * 128 + wm + mt * 16 + g;
            const int b = m0 >> 10, nr = m0 & 1023;
            float* p = G + (((size_t)b * 12 + head) * 1024 + nr) * 64 + d;
            *(float2*)p = make_float2(acc[mt][nt][0], acc[mt][nt][1]);
            *(float2*)(p + 8 * 64) = make_float2(acc[mt][nt][2], acc[mt][nt][3]);
        }
    }
}

// ---------------------------------------------------------------------------
// K2: dots = (scale*Q) @ K^T per (b,h). grid (8 jt, 8 it, 96 bh)
// As/Ks: [128][24] halfs hi + lo each. Scale folded into Q split (exact /8).
// ---------------------------------------------------------------------------
__global__ __launch_bounds__(256, 2) void k_dots() {
    __shared__ __half As[2 * 128 * 24];
    __shared__ __half Ks[2 * 128 * 24];
    const int tid = threadIdx.x, lane = tid & 31, w = tid >> 5;
    const int jt = blockIdx.x, it = blockIdx.y, bh = blockIdx.z;
    const float* Qp = g_Q + (size_t)bh * Nn * 64;
    const float* Kp = g_K + (size_t)bh * Nn * 64;
    float* Sp = g_S + (size_t)bh * Nn * Nn;
    const int wm = (w >> 2) * 64, wn = (w & 3) * 32;

    const int ar = tid >> 2, ak4 = (tid & 3) * 4;
    const float* Ap = Qp + ((size_t)it * 128 + ar) * 64 + ak4;
    const float* Bp = Kp + ((size_t)jt * 128 + ar) * 64 + ak4;

    const int lr = lane & 7, hs = (lane >> 3) & 1, kc = lane >> 4;
    const unsigned sa = (unsigned)__cvta_generic_to_shared(As);
    const unsigned sk = (unsigned)__cvta_generic_to_shared(Ks);
    const unsigned aaddr = sa + ((wm + hs * 8 + lr) * 24 + kc * 8) * 2;
    const unsigned kaddr = sk + ((wn + hs * 8 + lr) * 24 + kc * 8) * 2;
    const unsigned LO = 128 * 24 * 2;

    float acc[4][4][4] = {};

    float4 ra0 = *(const float4*)(Ap);
    float4 ra1 = *(const float4*)(Ap + 64 * 64);
    float4 rb0 = *(const float4*)(Bp);
    float4 rb1 = *(const float4*)(Bp + 64 * 64);

    for (int kt = 0; kt < 4; ++kt) {
        const float s = 0.125f;
        float4 qa0 = make_float4(ra0.x*s, ra0.y*s, ra0.z*s, ra0.w*s);
        float4 qa1 = make_float4(ra1.x*s, ra1.y*s, ra1.z*s, ra1.w*s);
        uint2 h, l;
        split4(qa0, h, l);
        *(uint2*)&As[ar * 24 + ak4] = h;           *(uint2*)&As[3072 + ar * 24 + ak4] = l;
        split4(qa1, h, l);
        *(uint2*)&As[(ar + 64) * 24 + ak4] = h;    *(uint2*)&As[3072 + (ar + 64) * 24 + ak4] = l;
        split4(rb0, h, l);
        *(uint2*)&Ks[ar * 24 + ak4] = h;           *(uint2*)&Ks[3072 + ar * 24 + ak4] = l;
        split4(rb1, h, l);
        *(uint2*)&Ks[(ar + 64) * 24 + ak4] = h;    *(uint2*)&Ks[3072 + (ar + 64) * 24 + ak4] = l;
        __syncthreads();
        if (kt < 3) {
            ra0 = *(const float4*)(Ap + (kt + 1) * 16);
            ra1 = *(const float4*)(Ap + 64 * 64 + (kt + 1) * 16);
            rb0 = *(const float4*)(Bp + (kt + 1) * 16);
            rb1 = *(const float4*)(Bp + 64 * 64 + (kt + 1) * 16);
        }
        unsigned af[4][4], bh[4][2], bl[4][2];
        #pragma unroll
        for (int mt = 0; mt < 4; ++mt)
            LDSM_X4(af[mt][0], af[mt][1], af[mt][2], af[mt][3], aaddr + mt * 768);
        #pragma unroll
        for (int n2 = 0; n2 < 2; ++n2) {
            // non-trans x4 on [n][k]: r0=b0(n0), r1=b0(n0+8), r2=b1(n0), r3=b1(n0+8)
            LDSM_X4(bh[2*n2][0], bh[2*n2+1][0], bh[2*n2][1], bh[2*n2+1][1], kaddr + n2 * 768);
            LDSM_X4(bl[2*n2][0], bl[2*n2+1][0], bl[2*n2][1], bl[2*n2+1][1], kaddr + n2 * 768 + LO);
        }
        #pragma unroll
        for (int mt = 0; mt < 4; ++mt)
            #pragma unroll
            for (int nt = 0; nt < 4; ++nt) {
                MMA16(acc[mt][nt], af[mt], bh[nt]);
                MMA16(acc[mt][nt], af[mt], bl[nt]);
            }
        #pragma unroll
        for (int mt = 0; mt < 4; ++mt)
            LDSM_X4(af[mt][0], af[mt][1], af[mt][2], af[mt][3], aaddr + mt * 768 + LO);
        #pragma unroll
        for (int mt = 0; mt < 4; ++mt)
            #pragma unroll
            for (int nt = 0; nt < 4; ++nt)
                MMA16(acc[mt][nt], af[mt], bh[nt]);
        __syncthreads();
    }

    const int g = lane >> 2, th = lane & 3;
    #pragma unroll
    for (int mt = 0; mt < 4; ++mt) {
        const int m = it * 128 + wm + mt * 16 + g;
        #pragma unroll
        for (int nt = 0; nt < 4; ++nt) {
            const int c = jt * 128 + wn + nt * 8 + 2 * th;
            *(float2*)(Sp + (size_t)m * 1024 + c) =
                make_float2(acc[mt][nt][0], acc[mt][nt][1]);
            *(float2*)(Sp + (size_t)(m + 8) * 1024 + c) =
                make_float2(acc[mt][nt][2], acc[mt][nt][3]);
        }
    }
}

// ---------------------------------------------------------------------------
// K3: mix_pre -> softmax -> mix_post, fused, in-place on g_S.
// ---------------------------------------------------------------------------
__global__ __launch_bounds__(256) void k_mixsoft(const float* __restrict__ mix_pre,
                                                 const float* __restrict__ mix_post) {
    __shared__ float raw[12 * 512];
    __shared__ float pre[144], post[144];
    __shared__ float wred[96];
    __shared__ float gstat[24];
    const int t = threadIdx.x;
    const int b = blockIdx.x >> 10, i = blockIdx.x & 1023;
    if (t < 144) { pre[t] = mix_pre[t]; post[t] = mix_post[t]; }
    const size_t rowbase = (size_t)b * 12 * 1048576 + (size_t)i * 1024;

    float mx[12][4];
    #pragma unroll
    for (int g = 0; g < 12; ++g)
        mx[g][0] = mx[g][1] = mx[g][2] = mx[g][3] = 0.f;

    #pragma unroll
    for (int c = 0; c < 2; ++c) {
        __syncthreads();
        #pragma unroll
        for (int u = 0; u < 24; ++u) {
            int idx = u * 256 + t;
            int h = idx >> 9, j = idx & 511;
            raw[idx] = g_S[rowbase + (size_t)h * 1048576 + c * 512 + j];
        }
        __syncthreads();
        float rv[12][2];
        #pragma unroll
        for (int h = 0; h < 12; ++h) {
            rv[h][0] = raw[h * 512 + t];
            rv[h][1] = raw[h * 512 + t + 256];
        }
        #pragma unroll
        for (int g = 0; g < 12; ++g) {
            float a0 = mx[g][c * 2], a1 = mx[g][c * 2 + 1];
            #pragma unroll
            for (int h = 0; h < 12; ++h) {
                float p = pre[h * 12 + g];
                a0 += rv[h][0] * p;
                a1 += rv[h][1] * p;
            }
            mx[g][c * 2] = a0; mx[g][c * 2 + 1] = a1;
        }
    }

    const int lane = t & 31, wid = t >> 5;
    #pragma unroll
    for (int g = 0; g < 12; ++g) {
        float m = fmaxf(fmaxf(mx[g][0], mx[g][1]), fmaxf(mx[g][2], mx[g][3]));
        #pragma unroll
        for (int o = 16; o > 0; o >>= 1) m = fmaxf(m, __shfl_xor_sync(0xffffffffu, m, o));
        if (lane == 0) wred[g * 8 + wid] = m;
    }
    __syncthreads();
    if (t < 12) {
        float m = wred[t * 8];
        #pragma unroll
        for (int w2 = 1; w2 < 8; ++w2) m = fmaxf(m, wred[t * 8 + w2]);
        gstat[t] = m;
    }
    __syncthreads();
    #pragma unroll
    for (int g = 0; g < 12; ++g) {
        float mg = gstat[g];
        float s = 0.f;
        #pragma unroll
        for (int r = 0; r < 4; ++r) { mx[g][r] = __expf(mx[g][r] - mg); s += mx[g][r]; }
        #pragma unroll
        for (int o = 16; o > 0; o >>= 1) s += __shfl_xor_sync(0xffffffffu, s, o);
        if (lane == 0) wred[g * 8 + wid] = s;
    }
    __syncthreads();
    if (t < 12) {
        float s = 0.f;
        #pragma unroll
        for (int w2 = 0; w2 < 8; ++w2) s += wred[t * 8 + w2];
        gstat[12 + t] = 1.0f / s;
    }
    __syncthreads();
    #pragma unroll
    for (int g = 0; g < 12; ++g) {
        float inv = gstat[12 + g];
        #pragma unroll
        for (int r = 0; r < 4; ++r) mx[g][r] *= inv;
    }
    #pragma unroll
    for (int h = 0; h < 12; ++h) {
        float o0 = 0.f, o1 = 0.f, o2 = 0.f, o3 = 0.f;
        #pragma unroll
        for (int g = 0; g < 12; ++g) {
            float p = post[g * 12 + h];
            o0 += mx[g][0] * p; o1 += mx[g][1] * p;
            o2 += mx[g][2] * p; o3 += mx[g][3] * p;
        }
        float* dst = g_S + rowbase + (size_t)h * 1048576;
        dst[t]       = o0; dst[t + 256] = o1;
        dst[t + 512] = o2; dst[t + 768] = o3;
    }
}

// ---------------------------------------------------------------------------
// K4: O = attn @ V per (b,h) -> g_C [b,n,h*64+d]. grid (8 it, 96 bh)
// Warps 4m x 2n: MT=2 (32 rows), NT=4 (32 cols).
// ---------------------------------------------------------------------------
__global__ __launch_bounds__(256, 2) void k_av() {
    __shared__ __half As[2 * 128 * 24];
    __shared__ __half Bs[2 * 16 * 72];
    const int tid = threadIdx.x, lane = tid & 31, w = tid >> 5;
    const int it = blockIdx.x, bh = blockIdx.y;
    const int b = bh / 12, h = bh % 12;
    const float* Apm = g_S + (size_t)bh * Nn * Nn + (size_t)it * 128 * 1024;
    const float* Vp  = g_V + (size_t)bh * Nn * 64;
    const int wm = (w >> 1) * 32, wn = (w & 1) * 32;

    const int ar = tid >> 2, ak4 = (tid & 3) * 4;
    const int bk = tid >> 4, bn4 = (tid & 15) * 4;
    const float* Ap = Apm + (size_t)ar * 1024 + ak4;

    const int lr = lane & 7, hs = (lane >> 3) & 1, kc = lane >> 4;
    const unsigned sa = (unsigned)__cvta_generic_to_shared(As);
    const unsigned sb = (unsigned)__cvta_generic_to_shared(Bs);
    const unsigned aaddr = sa + ((wm + hs * 8 + lr) * 24 + kc * 8) * 2;
    const unsigned baddr = sb + ((hs * 8 + lr) * 72 + wn + kc * 8) * 2;
    const unsigned ALO = 128 * 24 * 2, BLO = 16 * 72 * 2;

    float acc[2][4][4] = {};

    float4 ra0 = *(const float4*)(Ap);
    float4 ra1 = *(const float4*)(Ap + (size_t)64 * 1024);
    float4 rb0 = *(const float4*)(Vp + (size_t)bk * 64 + bn4);

    for (int kt = 0; kt < 64; ++kt) {
        uint2 hh, ll;
        split4(ra0, hh, ll);
        *(uint2*)&As[ar * 24 + ak4] = hh;          *(uint2*)&As[3072 + ar * 24 + ak4] = ll;
        split4(ra1, hh, ll);
        *(uint2*)&As[(ar + 64) * 24 + ak4] = hh;   *(uint2*)&As[3072 + (ar + 64) * 24 + ak4] = ll;
        split4(rb0, hh, ll);
        *(uint2*)&Bs[bk * 72 + bn4] = hh;          *(uint2*)&Bs[1152 + bk * 72 + bn4] = ll;
        __syncthreads();
        if (kt < 63) {
            ra0 = *(const float4*)(Ap + (kt + 1) * 16);
            ra1 = *(const float4*)(Ap + (size_t)64 * 1024 + (kt + 1) * 16);
            rb0 = *(const float4*)(Vp + (size_t)((kt + 1) * 16 + bk) * 64 + bn4);
        }
        unsigned af[2][4], bh2[4][2], bl2[4][2];
        #pragma unroll
        for (int mt = 0; mt < 2; ++mt)
            LDSM_X4(af[mt][0], af[mt][1], af[mt][2], af[mt][3], aaddr + mt * 768);
        #pragma unroll
        for (int n2 = 0; n2 < 2; ++n2) {
            LDSM_X4T(bh2[2*n2][0], bh2[2*n2][1], bh2[2*n2+1][0], bh2[2*n2+1][1], baddr + n2 * 32);
            LDSM_X4T(bl2[2*n2][0], bl2[2*n2][1], bl2[2*n2+1][0], bl2[2*n2+1][1], baddr + n2 * 32 + BLO);
        }
        #pragma unroll
        for (int mt = 0; mt < 2; ++mt)
            #pragma unroll
            for (int nt = 0; nt < 4; ++nt) {
                MMA16(acc[mt][nt], af[mt], bh2[nt]);
                MMA16(acc[mt][nt], af[mt], bl2[nt]);
            }
        #pragma unroll
        for (int mt = 0; mt < 2; ++mt)
            LDSM_X4(af[mt][0], af[mt][1], af[mt][2], af[mt][3], aaddr + mt * 768 + ALO);
        #pragma unroll
        for (int mt = 0; mt < 2; ++mt)
            #pragma unroll
            for (int nt = 0; nt < 4; ++nt)
                MMA16(acc[mt][nt], af[mt], bh2[nt]);
        __syncthreads();
    }

    const int g = lane >> 2, th = lane & 3;
    #pragma unroll
    for (int mt = 0; mt < 2; ++mt) {
        const int m = it * 128 + wm + mt * 16 + g;
        #pragma unroll
        for (int nt = 0; nt < 4; ++nt) {
            const int c = wn + nt * 8 + 2 * th;
            float* p = g_C + ((size_t)b * 1024 + m) * 768 + h * 64 + c;
            *(float2*)p = make_float2(acc[mt][nt][0], acc[mt][nt][1]);
            *(float2*)(p + (size_t)8 * 768) = make_float2(acc[mt][nt][2], acc[mt][nt][3]);
        }
    }
}

// ---------------------------------------------------------------------------
// K5: out = Ctx @ Wo + bo. grid (6, 64)
// ---------------------------------------------------------------------------
__global__ __launch_bounds__(256, 2) void k_out(const float* __restrict__ Wo,
                                                const float* __restrict__ bo,
                                                float* __restrict__ out) {
    __shared__ __half As[2 * 128 * 24];
    __shared__ __half Bs[2 * 16 * 136];
    const int tid = threadIdx.x, lane = tid & 31, w = tid >> 5;
    const int bx = blockIdx.x, by = blockIdx.y;
    const float* Bp = Wo + bx * 128;
    const int wm = (w >> 2) * 64, wn = (w & 3) * 32;

    const int ar = tid >> 2, ak4 = (tid & 3) * 4;
    const int bk = tid >> 4, bn4 = (tid & 15) * 4;
    const float* Ap = g_C + ((size_t)by * 128 + ar) * 768 + ak4;

    const int lr = lane & 7, hs = (lane >> 3) & 1, kc = lane >> 4;
    const unsigned sa = (unsigned)__cvta_generic_to_shared(As);
    const unsigned sb = (unsigned)__cvta_generic_to_shared(Bs);
    const unsigned aaddr = sa + ((wm + hs * 8 + lr) * 24 + kc * 8) * 2;
    const unsigned baddr = sb + ((hs * 8 + lr) * 136 + wn + kc * 8) * 2;
    const unsigned ALO = 128 * 24 * 2, BLO = 16 * 136 * 2;

    float acc[4][4][4] = {};

    float4 ra0 = *(const float4*)(Ap);
    float4 ra1 = *(const float4*)(Ap + (size_t)64 * 768);
    float4 rb0 = *(const float4*)(Bp + (size_t)bk * 768 + bn4);
    float4 rb1 = *(const float4*)(Bp + (size_t)bk * 768 + bn4 + 64);

    for (int kt = 0; kt < 48; ++kt) {
        uint2 h, l;
        split4(ra0, h, l);
        *(uint2*)&As[ar * 24 + ak4] = h;           *(uint2*)&As[3072 + ar * 24 + ak4] = l;
        split4(ra1, h, l);
        *(uint2*)&As[(ar + 64) * 24 + ak4] = h;    *(uint2*)&As[3072 + (ar + 64) * 24 + ak4] = l;
        split4(rb0, h, l);
        *(uint2*)&Bs[bk * 136 + bn4] = h;          *(uint2*)&Bs[2176 + bk * 136 + bn4] = l;
        split4(rb1, h, l);
        *(uint2*)&Bs[bk * 136 + bn4 + 64] = h;     *(uint2*)&Bs[2176 + bk * 136 + bn4 + 64] = l;
        __syncthreads();
        if (kt < 47) {
            ra0 = *(const float4*)(Ap + (kt + 1) * 16);
            ra1 = *(const float4*)(Ap + (size_t)64 * 768 + (kt + 1) * 16);
            rb0 = *(const float4*)(Bp + (size_t)((kt + 1) * 16 + bk) * 768 + bn4);
            rb1 = *(const float4*)(Bp + (size_t)((kt + 1) * 16 + bk) * 768 + bn4 + 64);
        }
        unsigned af[4][4], bh[4][2], bl[4][2];
        #pragma unroll
        for (int mt = 0; mt < 4; ++mt)
            LDSM_X4(af[mt][0], af[mt][1], af[mt][2], af[mt][3], aaddr + mt * 768);
        #pragma unroll
        for (int n2 = 0; n2 < 2; ++n2) {
            LDSM_X4T(bh[2*n2][0], bh[2*n2][1], bh[2*n2+1][0], bh[2*n2+1][1], baddr + n2 * 32);
            LDSM_X4T(bl[2*n2][0], bl[2*n2][1], bl[2*n2+1][0], bl[2*n2+1][1], baddr + n2 * 32 + BLO);
        }
        #pragma unroll
        for (int mt = 0; mt < 4; ++mt)
            #pragma unroll
            for (int nt = 0; nt < 4; ++nt) {
                MMA16(acc[mt][nt], af[mt], bh[nt]);
                MMA16(acc[mt][nt], af[mt], bl[nt]);
            }
        #pragma unroll
        for (int mt = 0; mt < 4; ++mt)
            LDSM_X4(af[mt][0], af[mt][1], af[mt][2], af[mt][3], aaddr + mt * 768 + ALO);
        #pragma unroll
        for (int mt = 0; mt < 4; ++mt)
            #pragma unroll
            for (int nt = 0; nt < 4; ++nt)
                MMA16(acc[mt][nt], af[mt], bh[nt]);
        __syncthreads();
    }

    const int g = lane >> 2, th = lane & 3;
    #pragma unroll
    for (int nt = 0; nt < 4; ++nt) {
        const int c = bx * 128 + wn + nt * 8 + 2 * th;
        const float b0v = bo[c], b1v = bo[c + 1];
        #pragma unroll
        for (int mt = 0; mt < 4; ++mt) {
            const int m = by * 128 + wm + mt * 16 + g;
            *(float2*)(out + (size_t)m * 768 + c) =
                make_float2(acc[mt][nt][0] + b0v, acc[mt][nt][1] + b1v);
            *(float2*)(out + (size_t)(m + 8) * 768 + c) =
                make_float2(acc[mt][nt][2] + b0v, acc[mt][nt][3] + b1v);
        }
    }
}

// ---------------------------------------------------------------------------
extern "C" void kernel_launch(void* const* d_in, const int* in_sizes, int n_in,
                              void* d_out, int out_size) {
    const float* x     = (const float*)d_in[0];
    const float* Wq    = (const float*)d_in[1];
    const float* Wkv   = (const float*)d_in[2];
    const float* mpre  = (const float*)d_in[3];
    const float* mpost = (const float*)d_in[4];
    const float* Wo    = (const float*)d_in[5];
    const float* bo    = (const float*)d_in[6];
    float* out = (float*)d_out;

    k_qkv    <<<dim3(18, 64),   256>>>(x, Wq, Wkv);
    k_dots   <<<dim3(8, 8, 96), 256>>>();
    k_mixsoft<<<8192,           256>>>(mpre, mpost);
    k_av     <<<dim3(8, 96),    256>>>();
    k_out    <<<dim3(6, 64),    256>>>(Wo, bo, out);
}

// round 5
// speedup vs baseline: 3.3031x; 1.0821x over previous
#include <cuda_runtime.h>
#include <cuda_fp16.h>
#include <math.h>

#define Bb 8
#define Nn 1024
#define Hh 12

#define QKVSZ ((size_t)Bb*Hh*Nn*64)

// Scratch (static device globals)
__device__ __half g_Qh[QKVSZ], g_Ql[QKVSZ];
__device__ __half g_Kh[QKVSZ], g_Kl[QKVSZ];
__device__ __half g_Vh[QKVSZ], g_Vl[QKVSZ];
__device__ float  g_S[(size_t)Bb*Hh*Nn*Nn];   // fp32 logits
__device__ __half g_P[(size_t)Bb*Hh*Nn*Nn];   // fp16 post-mixed attn
__device__ __half g_Ch[(size_t)Bb*Nn*768], g_Cl[(size_t)Bb*Nn*768];

// ---------------------------------------------------------------------------
__device__ __forceinline__ void split2(float a, float b, unsigned &h, unsigned &l) {
    __half ha = __float2half_rn(a), hb = __float2half_rn(b);
    __half2 H = __halves2half2(ha, hb);
    __half2 L = __halves2half2(__float2half_rn(a - __half2float(ha)),
                               __float2half_rn(b - __half2float(hb)));
    h = *(unsigned*)&H; l = *(unsigned*)&L;
}
__device__ __forceinline__ void split4(float4 v, uint2 &h, uint2 &l) {
    split2(v.x, v.y, h.x, l.x); split2(v.z, v.w, h.y, l.y);
}
__device__ __forceinline__ void store_hl(__half* Gh, __half* Gl, size_t idx,
                                         float v0, float v1) {
    __half h0 = __float2half_rn(v0), h1 = __float2half_rn(v1);
    __half l0 = __float2half_rn(v0 - __half2float(h0));
    __half l1 = __float2half_rn(v1 - __half2float(h1));
    *(__half2*)(Gh + idx) = __halves2half2(h0, h1);
    *(__half2*)(Gl + idx) = __halves2half2(l0, l1);
}

#define LDSM_X4(r0, r1, r2, r3, a) \
  asm volatile("ldmatrix.sync.aligned.m8n8.x4.shared.b16 {%0,%1,%2,%3},[%4];" \
               : "=r"(r0), "=r"(r1), "=r"(r2), "=r"(r3) : "r"(a))
#define LDSM_X4T(r0, r1, r2, r3, a) \
  asm volatile("ldmatrix.sync.aligned.m8n8.x4.trans.shared.b16 {%0,%1,%2,%3},[%4];" \
               : "=r"(r0), "=r"(r1), "=r"(r2), "=r"(r3) : "r"(a))
#define MMA16(c, a, b) \
  asm volatile("mma.sync.aligned.m16n8k16.row.col.f32.f16.f16.f32 " \
               "{%0,%1,%2,%3},{%4,%5,%6,%7},{%8,%9},{%0,%1,%2,%3};" \
               : "+f"(c[0]), "+f"(c[1]), "+f"(c[2]), "+f"(c[3]) \
               : "r"(a[0]), "r"(a[1]), "r"(a[2]), "r"(a[3]), "r"(b[0]), "r"(b[1]))

// ---------------------------------------------------------------------------
// K1: QKV projection. x[8192,768] @ [Wq|Wkv] -> pre-split hi/lo fp16 Q/K/V.
// grid (18, 64). Q gets the 1/8 softmax scale folded in (exact).
// ---------------------------------------------------------------------------
__global__ __launch_bounds__(256, 2) void k_qkv(const float* __restrict__ x,
                                                const float* __restrict__ Wq,
                                                const float* __restrict__ Wkv) {
    __shared__ __half As[2 * 128 * 24];
    __shared__ __half Bs[2 * 16 * 136];
    const int tid = threadIdx.x, lane = tid & 31, w = tid >> 5;
    const int bx = blockIdx.x, by = blockIdx.y;
    const int nglob = bx * 128;
    const float* Bp = (nglob < 768) ? (Wq + nglob) : (Wkv + (nglob - 768));
    const int ldb = (nglob < 768) ? 768 : 1536;
    const int wm = (w >> 2) * 64, wn = (w & 3) * 32;

    const int ar = tid >> 2, ak4 = (tid & 3) * 4;
    const int bk = tid >> 4, bn4 = (tid & 15) * 4;
    const float* Ap = x + ((size_t)by * 128 + ar) * 768 + ak4;

    const int lr = lane & 7, hs = (lane >> 3) & 1, kc = lane >> 4;
    const unsigned sa = (unsigned)__cvta_generic_to_shared(As);
    const unsigned sb = (unsigned)__cvta_generic_to_shared(Bs);
    const unsigned aaddr = sa + ((wm + hs * 8 + lr) * 24 + kc * 8) * 2;
    const unsigned baddr = sb + ((hs * 8 + lr) * 136 + wn + kc * 8) * 2;
    const unsigned ALO = 128 * 24 * 2, BLO = 16 * 136 * 2;

    float acc[4][4][4] = {};

    float4 ra0 = *(const float4*)(Ap);
    float4 ra1 = *(const float4*)(Ap + (size_t)64 * 768);
    float4 rb0 = *(const float4*)(Bp + (size_t)bk * ldb + bn4);
    float4 rb1 = *(const float4*)(Bp + (size_t)bk * ldb + bn4 + 64);

    for (int kt = 0; kt < 48; ++kt) {
        uint2 h, l;
        split4(ra0, h, l);
        *(uint2*)&As[ar * 24 + ak4] = h;            *(uint2*)&As[3072 + ar * 24 + ak4] = l;
        split4(ra1, h, l);
        *(uint2*)&As[(ar + 64) * 24 + ak4] = h;     *(uint2*)&As[3072 + (ar + 64) * 24 + ak4] = l;
        split4(rb0, h, l);
        *(uint2*)&Bs[bk * 136 + bn4] = h;           *(uint2*)&Bs[2176 + bk * 136 + bn4] = l;
        split4(rb1, h, l);
        *(uint2*)&Bs[bk * 136 + bn4 + 64] = h;      *(uint2*)&Bs[2176 + bk * 136 + bn4 + 64] = l;
        __syncthreads();
        if (kt < 47) {
            ra0 = *(const float4*)(Ap + (kt + 1) * 16);
            ra1 = *(const float4*)(Ap + (size_t)64 * 768 + (kt + 1) * 16);
            rb0 = *(const float4*)(Bp + (size_t)((kt + 1) * 16 + bk) * ldb + bn4);
            rb1 = *(const float4*)(Bp + (size_t)((kt + 1) * 16 + bk) * ldb + bn4 + 64);
        }
        unsigned af[4][4], bh[4][2], bl[4][2];
        #pragma unroll
        for (int mt = 0; mt < 4; ++mt)
            LDSM_X4(af[mt][0], af[mt][1], af[mt][2], af[mt][3], aaddr + mt * 768);
        #pragma unroll
        for (int n2 = 0; n2 < 2; ++n2) {
            LDSM_X4T(bh[2*n2][0], bh[2*n2][1], bh[2*n2+1][0], bh[2*n2+1][1], baddr + n2 * 32);
            LDSM_X4T(bl[2*n2][0], bl[2*n2][1], bl[2*n2+1][0], bl[2*n2+1][1], baddr + n2 * 32 + BLO);
        }
        #pragma unroll
        for (int mt = 0; mt < 4; ++mt)
            #pragma unroll
            for (int nt = 0; nt < 4; ++nt) {
                MMA16(acc[mt][nt], af[mt], bh[nt]);
                MMA16(acc[mt][nt], af[mt], bl[nt]);
            }
        #pragma unroll
        for (int mt = 0; mt < 4; ++mt)
            LDSM_X4(af[mt][0], af[mt][1], af[mt][2], af[mt][3], aaddr + mt * 768 + ALO);
        #pragma unroll
        for (int mt = 0; mt < 4; ++mt)
            #pragma unroll
            for (int nt = 0; nt < 4; ++nt)
                MMA16(acc[mt][nt], af[mt], bh[nt]);
        __syncthreads();
    }

    const int g = lane >> 2, th = lane & 3;
    #pragma unroll
    for (int nt = 0; nt < 4; ++nt) {
        const int col = nglob + wn + nt * 8 + 2 * th;
        const int mat = col / 768;
        const int within = col - mat * 768;
        const int head = within >> 6, d = within & 63;
        __half* Gh = (mat == 0) ? g_Qh : (mat == 1) ? g_Kh : g_Vh;
        __half* Gl = (mat == 0) ? g_Ql : (mat == 1) ? g_Kl : g_Vl;
        const float sc = (mat == 0) ? 0.125f : 1.0f;
        #pragma unroll
        for (int mt = 0; mt < 4; ++mt) {
            const int m0 = by * 128 + wm + mt * 16 + g;
            const int b = m0 >> 10, nr = m0 & 1023;
            const size_t base = (((size_t)b * 12 + head) * 1024 + nr) * 64 + d;
            store_hl(Gh, Gl, base,            acc[mt][nt][0] * sc, acc[mt][nt][1] * sc);
            store_hl(Gh, Gl, base + 8 * 64,   acc[mt][nt][2] * sc, acc[mt][nt][3] * sc);
        }
    }
}

// ---------------------------------------------------------------------------
// K2: logits = (Q/8) @ K^T per (b,h), pre-split fp16 inputs. grid (8,8,96)
// ---------------------------------------------------------------------------
__global__ __launch_bounds__(256, 2) void k_dots() {
    __shared__ __half Qs[2 * 128 * 40];
    __shared__ __half Ks[2 * 128 * 40];
    const int tid = threadIdx.x, lane = tid & 31, w = tid >> 5;
    const int jt = blockIdx.x, it = blockIdx.y, bh = blockIdx.z;
    const __half* Qhp = g_Qh + (size_t)bh * 65536 + (size_t)it * 128 * 64;
    const __half* Qlp = g_Ql + (size_t)bh * 65536 + (size_t)it * 128 * 64;
    const __half* Khp = g_Kh + (size_t)bh * 65536 + (size_t)jt * 128 * 64;
    const __half* Klp = g_Kl + (size_t)bh * 65536 + (size_t)jt * 128 * 64;
    float* Sp = g_S + (size_t)bh * Nn * Nn;
    const int wm = (w >> 2) * 64, wn = (w & 3) * 32;

    const int lr = lane & 7, hs = (lane >> 3) & 1, kc = lane >> 4;
    const unsigned sq = (unsigned)__cvta_generic_to_shared(Qs);
    const unsigned sk = (unsigned)__cvta_generic_to_shared(Ks);
    const unsigned aaddr = sq + ((wm + hs * 8 + lr) * 40 + kc * 8) * 2;
    const unsigned kaddr = sk + ((wn + hs * 8 + lr) * 40 + kc * 8) * 2;
    const unsigned PLO = 128 * 40 * 2;  // bytes to lo plane

    float acc[4][4][4] = {};

    for (int kt = 0; kt < 2; ++kt) {
        #pragma unroll
        for (int j = 0; j < 2; ++j) {
            const int u = j * 256 + tid;
            const int row = u >> 2, c16 = u & 3;
            const int goff = row * 64 + kt * 32 + c16 * 8;
            const int soff = row * 40 + c16 * 8;
            *(uint4*)&Qs[soff]        = *(const uint4*)(Qhp + goff);
            *(uint4*)&Qs[5120 + soff] = *(const uint4*)(Qlp + goff);
            *(uint4*)&Ks[soff]        = *(const uint4*)(Khp + goff);
            *(uint4*)&Ks[5120 + soff] = *(const uint4*)(Klp + goff);
        }
        __syncthreads();
        #pragma unroll
        for (int kk = 0; kk < 32; kk += 16) {
            unsigned bkh[4][2], bkl[4][2], af[4][4];
            #pragma unroll
            for (int n2 = 0; n2 < 2; ++n2) {
                LDSM_X4(bkh[2*n2][0], bkh[2*n2+1][0], bkh[2*n2][1], bkh[2*n2+1][1],
                        kaddr + n2 * 1280 + kk * 2);
                LDSM_X4(bkl[2*n2][0], bkl[2*n2+1][0], bkl[2*n2][1], bkl[2*n2+1][1],
                        kaddr + n2 * 1280 + kk * 2 + PLO);
            }
            #pragma unroll
            for (int mt = 0; mt < 4; ++mt)
                LDSM_X4(af[mt][0], af[mt][1], af[mt][2], af[mt][3],
                        aaddr + mt * 1280 + kk * 2);
            #pragma unroll
            for (int mt = 0; mt < 4; ++mt)
                #pragma unroll
                for (int nt = 0; nt < 4; ++nt) {
                    MMA16(acc[mt][nt], af[mt], bkh[nt]);
                    MMA16(acc[mt][nt], af[mt], bkl[nt]);
                }
            #pragma unroll
            for (int mt = 0; mt < 4; ++mt)
                LDSM_X4(af[mt][0], af[mt][1], af[mt][2], af[mt][3],
                        aaddr + mt * 1280 + kk * 2 + PLO);
            #pragma unroll
            for (int mt = 0; mt < 4; ++mt)
                #pragma unroll
                for (int nt = 0; nt < 4; ++nt)
                    MMA16(acc[mt][nt], af[mt], bkh[nt]);
        }
        __syncthreads();
    }

    const int g = lane >> 2, th = lane & 3;
    #pragma unroll
    for (int mt = 0; mt < 4; ++mt) {
        const int m = it * 128 + wm + mt * 16 + g;
        #pragma unroll
        for (int nt = 0; nt < 4; ++nt) {
            const int c = jt * 128 + wn + nt * 8 + 2 * th;
            *(float2*)(Sp + (size_t)m * 1024 + c) =
                make_float2(acc[mt][nt][0], acc[mt][nt][1]);
            *(float2*)(Sp + (size_t)(m + 8) * 1024 + c) =
                make_float2(acc[mt][nt][2], acc[mt][nt][3]);
        }
    }
}

// ---------------------------------------------------------------------------
// K3: mix_pre -> softmax -> mix_post; reads fp32 g_S, writes fp16 g_P.
// ---------------------------------------------------------------------------
__global__ __launch_bounds__(256) void k_mixsoft(const float* __restrict__ mix_pre,
                                                 const float* __restrict__ mix_post) {
    __shared__ float raw[12 * 512];
    __shared__ float pre[144], post[144];
    __shared__ float wred[96];
    __shared__ float gstat[24];
    const int t = threadIdx.x;
    const int b = blockIdx.x >> 10, i = blockIdx.x & 1023;
    if (t < 144) { pre[t] = mix_pre[t]; post[t] = mix_post[t]; }
    const size_t rowbase = (size_t)b * 12 * 1048576 + (size_t)i * 1024;

    float mx[12][4];
    #pragma unroll
    for (int g = 0; g < 12; ++g)
        mx[g][0] = mx[g][1] = mx[g][2] = mx[g][3] = 0.f;

    #pragma unroll
    for (int c = 0; c < 2; ++c) {
        __syncthreads();
        #pragma unroll
        for (int u = 0; u < 24; ++u) {
            int idx = u * 256 + t;
            int h = idx >> 9, j = idx & 511;
            raw[idx] = g_S[rowbase + (size_t)h * 1048576 + c * 512 + j];
        }
        __syncthreads();
        float rv[12][2];
        #pragma unroll
        for (int h = 0; h < 12; ++h) {
            rv[h][0] = raw[h * 512 + t];
            rv[h][1] = raw[h * 512 + t + 256];
        }
        #pragma unroll
        for (int g = 0; g < 12; ++g) {
            float a0 = mx[g][c * 2], a1 = mx[g][c * 2 + 1];
            #pragma unroll
            for (int h = 0; h < 12; ++h) {
                float p = pre[h * 12 + g];
                a0 += rv[h][0] * p;
                a1 += rv[h][1] * p;
            }
            mx[g][c * 2] = a0; mx[g][c * 2 + 1] = a1;
        }
    }

    const int lane = t & 31, wid = t >> 5;
    #pragma unroll
    for (int g = 0; g < 12; ++g) {
        float m = fmaxf(fmaxf(mx[g][0], mx[g][1]), fmaxf(mx[g][2], mx[g][3]));
        #pragma unroll
        for (int o = 16; o > 0; o >>= 1) m = fmaxf(m, __shfl_xor_sync(0xffffffffu, m, o));
        if (lane == 0) wred[g * 8 + wid] = m;
    }
    __syncthreads();
    if (t < 12) {
        float m = wred[t * 8];
        #pragma unroll
        for (int w2 = 1; w2 < 8; ++w2) m = fmaxf(m, wred[t * 8 + w2]);
        gstat[t] = m;
    }
    __syncthreads();
    #pragma unroll
    for (int g = 0; g < 12; ++g) {
        float mg = gstat[g];
        float s = 0.f;
        #pragma unroll
        for (int r = 0; r < 4; ++r) { mx[g][r] = __expf(mx[g][r] - mg); s += mx[g][r]; }
        #pragma unroll
        for (int o = 16; o > 0; o >>= 1) s += __shfl_xor_sync(0xffffffffu, s, o);
        if (lane == 0) wred[g * 8 + wid] = s;
    }
    __syncthreads();
    if (t < 12) {
        float s = 0.f;
        #pragma unroll
        for (int w2 = 0; w2 < 8; ++w2) s += wred[t * 8 + w2];
        gstat[12 + t] = 1.0f / s;
    }
    __syncthreads();
    #pragma unroll
    for (int g = 0; g < 12; ++g) {
        float inv = gstat[12 + g];
        #pragma unroll
        for (int r = 0; r < 4; ++r) mx[g][r] *= inv;
    }
    #pragma unroll
    for (int h = 0; h < 12; ++h) {
        float o0 = 0.f, o1 = 0.f, o2 = 0.f, o3 = 0.f;
        #pragma unroll
        for (int g = 0; g < 12; ++g) {
            float p = post[g * 12 + h];
            o0 += mx[g][0] * p; o1 += mx[g][1] * p;
            o2 += mx[g][2] * p; o3 += mx[g][3] * p;
        }
        __half* dst = g_P + rowbase + (size_t)h * 1048576;
        dst[t]       = __float2half_rn(o0);
        dst[t + 256] = __float2half_rn(o1);
        dst[t + 512] = __float2half_rn(o2);
        dst[t + 768] = __float2half_rn(o3);
    }
}

// ---------------------------------------------------------------------------
// K4: O = attn(fp16) @ V(hi/lo) per (b,h) -> g_Ch/g_Cl. grid (8 it, 96 bh)
// Only 2 mma passes: A*Vhi + A*Vlo. No split ALU.
// ---------------------------------------------------------------------------
__global__ __launch_bounds__(256, 2) void k_av() {
    __shared__ __half As[128 * 40];
    __shared__ __half Vs[2 * 32 * 72];
    const int tid = threadIdx.x, lane = tid & 31, w = tid >> 5;
    const int it = blockIdx.x, bh = blockIdx.y;
    const int b = bh / 12, h = bh % 12;
    const __half* Pp  = g_P  + (size_t)bh * 1048576 + (size_t)it * 131072;
    const __half* Vhp = g_Vh + (size_t)bh * 65536;
    const __half* Vlp = g_Vl + (size_t)bh * 65536;
    const int wm = (w >> 1) * 32, wn = (w & 1) * 32;

    const int arow = tid >> 2, ac16 = tid & 3;   // A rows 0..63 (+64)
    const int vrow = tid >> 3, vc16 = tid & 7;   // V rows 0..31

    const int lr = lane & 7, hs = (lane >> 3) & 1, kc = lane >> 4;
    const unsigned sa = (unsigned)__cvta_generic_to_shared(As);
    const unsigned sb = (unsigned)__cvta_generic_to_shared(Vs);
    const unsigned aaddr = sa + ((wm + hs * 8 + lr) * 40 + kc * 8) * 2;
    const unsigned baddr = sb + ((hs * 8 + lr) * 72 + wn + kc * 8) * 2;
    const unsigned VLOB = 32 * 72 * 2;

    float acc[2][4][4] = {};

    uint4 pa0 = *(const uint4*)(Pp + (size_t)arow * 1024 + ac16 * 8);
    uint4 pa1 = *(const uint4*)(Pp + (size_t)(arow + 64) * 1024 + ac16 * 8);
    uint4 pv0 = *(const uint4*)(Vhp + vrow * 64 + vc16 * 8);
    uint4 pv1 = *(const uint4*)(Vlp + vrow * 64 + vc16 * 8);

    for (int kt = 0; kt < 32; ++kt) {
        *(uint4*)&As[arow * 40 + ac16 * 8]        = pa0;
        *(uint4*)&As[(arow + 64) * 40 + ac16 * 8] = pa1;
        *(uint4*)&Vs[vrow * 72 + vc16 * 8]        = pv0;
        *(uint4*)&Vs[2304 + vrow * 72 + vc16 * 8] = pv1;
        __syncthreads();
        if (kt < 31) {
            pa0 = *(const uint4*)(Pp + (size_t)arow * 1024 + (kt + 1) * 32 + ac16 * 8);
            pa1 = *(const uint4*)(Pp + (size_t)(arow + 64) * 1024 + (kt + 1) * 32 + ac16 * 8);
            pv0 = *(const uint4*)(Vhp + (size_t)((kt + 1) * 32 + vrow) * 64 + vc16 * 8);
            pv1 = *(const uint4*)(Vlp + (size_t)((kt + 1) * 32 + vrow) * 64 + vc16 * 8);
        }
        #pragma unroll
        for (int kk = 0; kk < 32; kk += 16) {
            unsigned af[2][4], bvh[4][2], bvl[4][2];
            #pragma unroll
            for (int n2 = 0; n2 < 2; ++n2) {
                LDSM_X4T(bvh[2*n2][0], bvh[2*n2][1], bvh[2*n2+1][0], bvh[2*n2+1][1],
                         baddr + kk * 144 + n2 * 32);
                LDSM_X4T(bvl[2*n2][0], bvl[2*n2][1], bvl[2*n2+1][0], bvl[2*n2+1][1],
                         baddr + kk * 144 + n2 * 32 + VLOB);
            }
            #pragma unroll
            for (int mt = 0; mt < 2; ++mt)
                LDSM_X4(af[mt][0], af[mt][1], af[mt][2], af[mt][3],
                        aaddr + mt * 1280 + kk * 2);
            #pragma unroll
            for (int mt = 0; mt < 2; ++mt)
                #pragma unroll
                for (int nt = 0; nt < 4; ++nt) {
                    MMA16(acc[mt][nt], af[mt], bvh[nt]);
                    MMA16(acc[mt][nt], af[mt], bvl[nt]);
                }
        }
        __syncthreads();
    }

    const int g = lane >> 2, th = lane & 3;
    #pragma unroll
    for (int mt = 0; mt < 2; ++mt) {
        const int m = it * 128 + wm + mt * 16 + g;
        #pragma unroll
        for (int nt = 0; nt < 4; ++nt) {
            const int c = wn + nt * 8 + 2 * th;
            const size_t base = ((size_t)b * 1024 + m) * 768 + h * 64 + c;
            store_hl(g_Ch, g_Cl, base,             acc[mt][nt][0], acc[mt][nt][1]);
            store_hl(g_Ch, g_Cl, base + 8 * 768,   acc[mt][nt][2], acc[mt][nt][3]);
        }
    }
}

// ---------------------------------------------------------------------------
// K5: out = Ctx(hi/lo fp16) @ Wo + bo. grid (6, 64)
// ---------------------------------------------------------------------------
__global__ __launch_bounds__(256, 2) void k_out(const float* __restrict__ Wo,
                                                const float* __restrict__ bo,
                                                float* __restrict__ out) {
    __shared__ __half As[2 * 128 * 24];
    __shared__ __half Bs[2 * 16 * 136];
    const int tid = threadIdx.x, lane = tid & 31, w = tid >> 5;
    const int bx = blockIdx.x, by = blockIdx.y;
    const float* Bp = Wo + bx * 128;
    const int wm = (w >> 2) * 64, wn = (w & 3) * 32;

    const int arow = tid >> 1, ac16 = tid & 1;
    const int bk = tid >> 4, bn4 = (tid & 15) * 4;
    const __half* Chp = g_Ch + (size_t)by * 128 * 768;
    const __half* Clp = g_Cl + (size_t)by * 128 * 768;

    const int lr = lane & 7, hs = (lane >> 3) & 1, kc = lane >> 4;
    const unsigned sa = (unsigned)__cvta_generic_to_shared(As);
    const unsigned sb = (unsigned)__cvta_generic_to_shared(Bs);
    const unsigned aaddr = sa + ((wm + hs * 8 + lr) * 24 + kc * 8) * 2;
    const unsigned baddr = sb + ((hs * 8 + lr) * 136 + wn + kc * 8) * 2;
    const unsigned ALO = 128 * 24 * 2, BLO = 16 * 136 * 2;

    float acc[4][4][4] = {};

    uint4 rah = *(const uint4*)(Chp + (size_t)arow * 768 + ac16 * 8);
    uint4 ral = *(const uint4*)(Clp + (size_t)arow * 768 + ac16 * 8);
    float4 rb0 = *(const float4*)(Bp + (size_t)bk * 768 + bn4);
    float4 rb1 = *(const float4*)(Bp + (size_t)bk * 768 + bn4 + 64);

    for (int kt = 0; kt < 48; ++kt) {
        *(uint4*)&As[arow * 24 + ac16 * 8]        = rah;
        *(uint4*)&As[3072 + arow * 24 + ac16 * 8] = ral;
        uint2 h, l;
        split4(rb0, h, l);
        *(uint2*)&Bs[bk * 136 + bn4] = h;          *(uint2*)&Bs[2176 + bk * 136 + bn4] = l;
        split4(rb1, h, l);
        *(uint2*)&Bs[bk * 136 + bn4 + 64] = h;     *(uint2*)&Bs[2176 + bk * 136 + bn4 + 64] = l;
        __syncthreads();
        if (kt < 47) {
            rah = *(const uint4*)(Chp + (size_t)arow * 768 + (kt + 1) * 16 + ac16 * 8);
            ral = *(const uint4*)(Clp + (size_t)arow * 768 + (kt + 1) * 16 + ac16 * 8);
            rb0 = *(const float4*)(Bp + (size_t)((kt + 1) * 16 + bk) * 768 + bn4);
            rb1 = *(const float4*)(Bp + (size_t)((kt + 1) * 16 + bk) * 768 + bn4 + 64);
        }
        unsigned af[4][4], bh[4][2], bl[4][2];
        #pragma unroll
        for (int mt = 0; mt < 4; ++mt)
            LDSM_X4(af[mt][0], af[mt][1], af[mt][2], af[mt][3], aaddr + mt * 768);
        #pragma unroll
        for (int n2 = 0; n2 < 2; ++n2) {
            LDSM_X4T(bh[2*n2][0], bh[2*n2][1], bh[2*n2+1][0], bh[2*n2+1][1], baddr + n2 * 32);
            LDSM_X4T(bl[2*n2][0], bl[2*n2][1], bl[2*n2+1][0], bl[2*n2+1][1], baddr + n2 * 32 + BLO);
        }
        #pragma unroll
        for (int mt = 0; mt < 4; ++mt)
            #pragma unroll
            for (int nt = 0; nt < 4; ++nt) {
                MMA16(acc[mt][nt], af[mt], bh[nt]);
                MMA16(acc[mt][nt], af[mt], bl[nt]);
            }
        #pragma unroll
        for (int mt = 0; mt < 4; ++mt)
            LDSM_X4(af[mt][0], af[mt][1], af[mt][2], af[mt][3], aaddr + mt * 768 + ALO);
        #pragma unroll
        for (int mt = 0; mt < 4; ++mt)
            #pragma unroll
            for (int nt = 0; nt < 4; ++nt)
                MMA16(acc[mt][nt], af[mt], bh[nt]);
        __syncthreads();
    }

    const int g = lane >> 2, th = lane & 3;
    #pragma unroll
    for (int nt = 0; nt < 4; ++nt) {
        const int c = bx * 128 + wn + nt * 8 + 2 * th;
        const float b0v = bo[c], b1v = bo[c + 1];
        #pragma unroll
        for (int mt = 0; mt < 4; ++mt) {
            const int m = by * 128 + wm + mt * 16 + g;
            *(float2*)(out + (size_t)m * 768 + c) =
                make_float2(acc[mt][nt][0] + b0v, acc[mt][nt][1] + b1v);
            *(float2*)(out + (size_t)(m + 8) * 768 + c) =
                make_float2(acc[mt][nt][2] + b0v, acc[mt][nt][3] + b1v);
        }
    }
}

// ---------------------------------------------------------------------------
extern "C" void kernel_launch(void* const* d_in, const int* in_sizes, int n_in,
                              void* d_out, int out_size) {
    const float* x     = (const float*)d_in[0];
    const float* Wq    = (const float*)d_in[1];
    const float* Wkv   = (const float*)d_in[2];
    const float* mpre  = (const float*)d_in[3];
    const float* mpost = (const float*)d_in[4];
    const float* Wo    = (const float*)d_in[5];
    const float* bo    = (const float*)d_in[6];
    float* out = (float*)d_out;

    k_qkv    <<<dim3(18, 64),   256>>>(x, Wq, Wkv);
    k_dots   <<<dim3(8, 8, 96), 256>>>();
    k_mixsoft<<<8192,           256>>>(mpre, mpost);
    k_av     <<<dim3(8, 96),    256>>>();
    k_out    <<<dim3(6, 64),    256>>>(Wo, bo, out);
}

// round 6
// speedup vs baseline: 3.4087x; 1.0320x over previous
#include <cuda_runtime.h>
#include <cuda_fp16.h>
#include <math.h>

#define Bb 8
#define Nn 1024
#define Hh 12

#define QKVSZ ((size_t)Bb*Hh*Nn*64)

// Scratch (static device globals)
__device__ __half g_Qh[QKVSZ], g_Ql[QKVSZ];
__device__ __half g_Kh[QKVSZ], g_Kl[QKVSZ];
__device__ __half g_Vh[QKVSZ], g_Vl[QKVSZ];
__device__ __half g_S[(size_t)Bb*Hh*Nn*Nn];   // fp16 raw logits
__device__ __half g_P[(size_t)Bb*Hh*Nn*Nn];   // fp16 post-mixed attn
__device__ __half g_Ch[(size_t)Bb*Nn*768], g_Cl[(size_t)Bb*Nn*768];

// ---------------------------------------------------------------------------
__device__ __forceinline__ void split2(float a, float b, unsigned &h, unsigned &l) {
    __half ha = __float2half_rn(a), hb = __float2half_rn(b);
    __half2 H = __halves2half2(ha, hb);
    __half2 L = __halves2half2(__float2half_rn(a - __half2float(ha)),
                               __float2half_rn(b - __half2float(hb)));
    h = *(unsigned*)&H; l = *(unsigned*)&L;
}
__device__ __forceinline__ void split4(float4 v, uint2 &h, uint2 &l) {
    split2(v.x, v.y, h.x, l.x); split2(v.z, v.w, h.y, l.y);
}
__device__ __forceinline__ void store_hl(__half* Gh, __half* Gl, size_t idx,
                                         float v0, float v1) {
    __half h0 = __float2half_rn(v0), h1 = __float2half_rn(v1);
    __half l0 = __float2half_rn(v0 - __half2float(h0));
    __half l1 = __float2half_rn(v1 - __half2float(h1));
    *(__half2*)(Gh + idx) = __halves2half2(h0, h1);
    *(__half2*)(Gl + idx) = __halves2half2(l0, l1);
}

#define LDSM_X4(r0, r1, r2, r3, a) \
  asm volatile("ldmatrix.sync.aligned.m8n8.x4.shared.b16 {%0,%1,%2,%3},[%4];" \
               : "=r"(r0), "=r"(r1), "=r"(r2), "=r"(r3) : "r"(a))
#define LDSM_X4T(r0, r1, r2, r3, a) \
  asm volatile("ldmatrix.sync.aligned.m8n8.x4.trans.shared.b16 {%0,%1,%2,%3},[%4];" \
               : "=r"(r0), "=r"(r1), "=r"(r2), "=r"(r3) : "r"(a))
#define MMA16(c, a, b) \
  asm volatile("mma.sync.aligned.m16n8k16.row.col.f32.f16.f16.f32 " \
               "{%0,%1,%2,%3},{%4,%5,%6,%7},{%8,%9},{%0,%1,%2,%3};" \
               : "+f"(c[0]), "+f"(c[1]), "+f"(c[2]), "+f"(c[3]) \
               : "r"(a[0]), "r"(a[1]), "r"(a[2]), "r"(a[3]), "r"(b[0]), "r"(b[1]))

// ---------------------------------------------------------------------------
// K1: QKV projection. x[8192,768] @ [Wq|Wkv] -> pre-split hi/lo fp16 Q/K/V.
// grid (18, 64). Q gets the 1/8 softmax scale folded in (exact).
// ---------------------------------------------------------------------------
__global__ __launch_bounds__(256, 2) void k_qkv(const float* __restrict__ x,
                                                const float* __restrict__ Wq,
                                                const float* __restrict__ Wkv) {
    __shared__ __half As[2 * 128 * 24];
    __shared__ __half Bs[2 * 16 * 136];
    const int tid = threadIdx.x, lane = tid & 31, w = tid >> 5;
    const int bx = blockIdx.x, by = blockIdx.y;
    const int nglob = bx * 128;
    const float* Bp = (nglob < 768) ? (Wq + nglob) : (Wkv + (nglob - 768));
    const int ldb = (nglob < 768) ? 768 : 1536;
    const int wm = (w >> 2) * 64, wn = (w & 3) * 32;

    const int ar = tid >> 2, ak4 = (tid & 3) * 4;
    const int bk = tid >> 4, bn4 = (tid & 15) * 4;
    const float* Ap = x + ((size_t)by * 128 + ar) * 768 + ak4;

    const int lr = lane & 7, hs = (lane >> 3) & 1, kc = lane >> 4;
    const unsigned sa = (unsigned)__cvta_generic_to_shared(As);
    const unsigned sb = (unsigned)__cvta_generic_to_shared(Bs);
    const unsigned aaddr = sa + ((wm + hs * 8 + lr) * 24 + kc * 8) * 2;
    const unsigned baddr = sb + ((hs * 8 + lr) * 136 + wn + kc * 8) * 2;
    const unsigned ALO = 128 * 24 * 2, BLO = 16 * 136 * 2;

    float acc[4][4][4] = {};

    float4 ra0 = *(const float4*)(Ap);
    float4 ra1 = *(const float4*)(Ap + (size_t)64 * 768);
    float4 rb0 = *(const float4*)(Bp + (size_t)bk * ldb + bn4);
    float4 rb1 = *(const float4*)(Bp + (size_t)bk * ldb + bn4 + 64);

    for (int kt = 0; kt < 48; ++kt) {
        uint2 h, l;
        split4(ra0, h, l);
        *(uint2*)&As[ar * 24 + ak4] = h;            *(uint2*)&As[3072 + ar * 24 + ak4] = l;
        split4(ra1, h, l);
        *(uint2*)&As[(ar + 64) * 24 + ak4] = h;     *(uint2*)&As[3072 + (ar + 64) * 24 + ak4] = l;
        split4(rb0, h, l);
        *(uint2*)&Bs[bk * 136 + bn4] = h;           *(uint2*)&Bs[2176 + bk * 136 + bn4] = l;
        split4(rb1, h, l);
        *(uint2*)&Bs[bk * 136 + bn4 + 64] = h;      *(uint2*)&Bs[2176 + bk * 136 + bn4 + 64] = l;
        __syncthreads();
        if (kt < 47) {
            ra0 = *(const float4*)(Ap + (kt + 1) * 16);
            ra1 = *(const float4*)(Ap + (size_t)64 * 768 + (kt + 1) * 16);
            rb0 = *(const float4*)(Bp + (size_t)((kt + 1) * 16 + bk) * ldb + bn4);
            rb1 = *(const float4*)(Bp + (size_t)((kt + 1) * 16 + bk) * ldb + bn4 + 64);
        }
        unsigned af[4][4], bh[4][2], bl[4][2];
        #pragma unroll
        for (int mt = 0; mt < 4; ++mt)
            LDSM_X4(af[mt][0], af[mt][1], af[mt][2], af[mt][3], aaddr + mt * 768);
        #pragma unroll
        for (int n2 = 0; n2 < 2; ++n2) {
            LDSM_X4T(bh[2*n2][0], bh[2*n2][1], bh[2*n2+1][0], bh[2*n2+1][1], baddr + n2 * 32);
            LDSM_X4T(bl[2*n2][0], bl[2*n2][1], bl[2*n2+1][0], bl[2*n2+1][1], baddr + n2 * 32 + BLO);
        }
        #pragma unroll
        for (int mt = 0; mt < 4; ++mt)
            #pragma unroll
            for (int nt = 0; nt < 4; ++nt) {
                MMA16(acc[mt][nt], af[mt], bh[nt]);
                MMA16(acc[mt][nt], af[mt], bl[nt]);
            }
        #pragma unroll
        for (int mt = 0; mt < 4; ++mt)
            LDSM_X4(af[mt][0], af[mt][1], af[mt][2], af[mt][3], aaddr + mt * 768 + ALO);
        #pragma unroll
        for (int mt = 0; mt < 4; ++mt)
            #pragma unroll
            for (int nt = 0; nt < 4; ++nt)
                MMA16(acc[mt][nt], af[mt], bh[nt]);
        __syncthreads();
    }

    const int g = lane >> 2, th = lane & 3;
    #pragma unroll
    for (int nt = 0; nt < 4; ++nt) {
        const int col = nglob + wn + nt * 8 + 2 * th;
        const int mat = col / 768;
        const int within = col - mat * 768;
        const int head = within >> 6, d = within & 63;
        __half* Gh = (mat == 0) ? g_Qh : (mat == 1) ? g_Kh : g_Vh;
        __half* Gl = (mat == 0) ? g_Ql : (mat == 1) ? g_Kl : g_Vl;
        const float sc = (mat == 0) ? 0.125f : 1.0f;
        #pragma unroll
        for (int mt = 0; mt < 4; ++mt) {
            const int m0 = by * 128 + wm + mt * 16 + g;
            const int b = m0 >> 10, nr = m0 & 1023;
            const size_t base = (((size_t)b * 12 + head) * 1024 + nr) * 64 + d;
            store_hl(Gh, Gl, base,            acc[mt][nt][0] * sc, acc[mt][nt][1] * sc);
            store_hl(Gh, Gl, base + 8 * 64,   acc[mt][nt][2] * sc, acc[mt][nt][3] * sc);
        }
    }
}

// ---------------------------------------------------------------------------
// K2: logits = (Q/8) @ K^T per (b,h), pre-split fp16 inputs -> fp16 g_S.
// grid (8,8,96)
// ---------------------------------------------------------------------------
__global__ __launch_bounds__(256, 2) void k_dots() {
    __shared__ __half Qs[2 * 128 * 40];
    __shared__ __half Ks[2 * 128 * 40];
    const int tid = threadIdx.x, lane = tid & 31, w = tid >> 5;
    const int jt = blockIdx.x, it = blockIdx.y, bh = blockIdx.z;
    const __half* Qhp = g_Qh + (size_t)bh * 65536 + (size_t)it * 128 * 64;
    const __half* Qlp = g_Ql + (size_t)bh * 65536 + (size_t)it * 128 * 64;
    const __half* Khp = g_Kh + (size_t)bh * 65536 + (size_t)jt * 128 * 64;
    const __half* Klp = g_Kl + (size_t)bh * 65536 + (size_t)jt * 128 * 64;
    __half* Sp = g_S + (size_t)bh * Nn * Nn;
    const int wm = (w >> 2) * 64, wn = (w & 3) * 32;

    const int lr = lane & 7, hs = (lane >> 3) & 1, kc = lane >> 4;
    const unsigned sq = (unsigned)__cvta_generic_to_shared(Qs);
    const unsigned sk = (unsigned)__cvta_generic_to_shared(Ks);
    const unsigned aaddr = sq + ((wm + hs * 8 + lr) * 40 + kc * 8) * 2;
    const unsigned kaddr = sk + ((wn + hs * 8 + lr) * 40 + kc * 8) * 2;
    const unsigned PLO = 128 * 40 * 2;  // bytes to lo plane

    float acc[4][4][4] = {};

    for (int kt = 0; kt < 2; ++kt) {
        #pragma unroll
        for (int j = 0; j < 2; ++j) {
            const int u = j * 256 + tid;
            const int row = u >> 2, c16 = u & 3;
            const int goff = row * 64 + kt * 32 + c16 * 8;
            const int soff = row * 40 + c16 * 8;
            *(uint4*)&Qs[soff]        = *(const uint4*)(Qhp + goff);
            *(uint4*)&Qs[5120 + soff] = *(const uint4*)(Qlp + goff);
            *(uint4*)&Ks[soff]        = *(const uint4*)(Khp + goff);
            *(uint4*)&Ks[5120 + soff] = *(const uint4*)(Klp + goff);
        }
        __syncthreads();
        #pragma unroll
        for (int kk = 0; kk < 32; kk += 16) {
            unsigned bkh[4][2], bkl[4][2], af[4][4];
            #pragma unroll
            for (int n2 = 0; n2 < 2; ++n2) {
                LDSM_X4(bkh[2*n2][0], bkh[2*n2+1][0], bkh[2*n2][1], bkh[2*n2+1][1],
                        kaddr + n2 * 1280 + kk * 2);
                LDSM_X4(bkl[2*n2][0], bkl[2*n2+1][0], bkl[2*n2][1], bkl[2*n2+1][1],
                        kaddr + n2 * 1280 + kk * 2 + PLO);
            }
            #pragma unroll
            for (int mt = 0; mt < 4; ++mt)
                LDSM_X4(af[mt][0], af[mt][1], af[mt][2], af[mt][3],
                        aaddr + mt * 1280 + kk * 2);
            #pragma unroll
            for (int mt = 0; mt < 4; ++mt)
                #pragma unroll
                for (int nt = 0; nt < 4; ++nt) {
                    MMA16(acc[mt][nt], af[mt], bkh[nt]);
                    MMA16(acc[mt][nt], af[mt], bkl[nt]);
                }
            #pragma unroll
            for (int mt = 0; mt < 4; ++mt)
                LDSM_X4(af[mt][0], af[mt][1], af[mt][2], af[mt][3],
                        aaddr + mt * 1280 + kk * 2 + PLO);
            #pragma unroll
            for (int mt = 0; mt < 4; ++mt)
                #pragma unroll
                for (int nt = 0; nt < 4; ++nt)
                    MMA16(acc[mt][nt], af[mt], bkh[nt]);
        }
        __syncthreads();
    }

    const int g = lane >> 2, th = lane & 3;
    #pragma unroll
    for (int mt = 0; mt < 4; ++mt) {
        const int m = it * 128 + wm + mt * 16 + g;
        #pragma unroll
        for (int nt = 0; nt < 4; ++nt) {
            const int c = jt * 128 + wn + nt * 8 + 2 * th;
            *(__half2*)(Sp + (size_t)m * 1024 + c) =
                __floats2half2_rn(acc[mt][nt][0], acc[mt][nt][1]);
            *(__half2*)(Sp + (size_t)(m + 8) * 1024 + c) =
                __floats2half2_rn(acc[mt][nt][2], acc[mt][nt][3]);
        }
    }
}

// ---------------------------------------------------------------------------
// K3: mix_pre -> softmax -> mix_post; reads fp16 g_S, writes fp16 g_P.
// One CTA per (b,i); all 12 head-rows (12KB x2) staged in smem as halves.
// ---------------------------------------------------------------------------
__global__ __launch_bounds__(256) void k_mixsoft(const float* __restrict__ mix_pre,
                                                 const float* __restrict__ mix_post) {
    __shared__ __half raw[12 * 1024];
    __shared__ float pre[144], post[144];
    __shared__ float wred[96];
    __shared__ float gstat[24];
    const int t = threadIdx.x;
    const int b = blockIdx.x >> 10, i = blockIdx.x & 1023;
    if (t < 144) { pre[t] = mix_pre[t]; post[t] = mix_post[t]; }
    const size_t rowbase = (size_t)b * 12 * 1048576 + (size_t)i * 1024;

    // Stage all 12 head-rows (fp16) with uint4 loads: 1536 x 16B.
    #pragma unroll
    for (int u = 0; u < 6; ++u) {
        const int v = u * 256 + t;          // 0..1535
        const int h = v >> 7;               // 128 uint4 per row
        const int j8 = (v & 127) * 8;
        *(uint4*)&raw[h * 1024 + j8] =
            *(const uint4*)(g_S + rowbase + (size_t)h * 1048576 + j8);
    }
    __syncthreads();

    float mx[12][4];
    #pragma unroll
    for (int g = 0; g < 12; ++g)
        mx[g][0] = mx[g][1] = mx[g][2] = mx[g][3] = 0.f;

    #pragma unroll
    for (int c = 0; c < 2; ++c) {
        float rv[12][2];
        #pragma unroll
        for (int h = 0; h < 12; ++h) {
            rv[h][0] = __half2float(raw[h * 1024 + c * 512 + t]);
            rv[h][1] = __half2float(raw[h * 1024 + c * 512 + t + 256]);
        }
        #pragma unroll
        for (int g = 0; g < 12; ++g) {
            float a0 = mx[g][c * 2], a1 = mx[g][c * 2 + 1];
            #pragma unroll
            for (int h = 0; h < 12; ++h) {
                float p = pre[h * 12 + g];
                a0 += rv[h][0] * p;
                a1 += rv[h][1] * p;
            }
            mx[g][c * 2] = a0; mx[g][c * 2 + 1] = a1;
        }
    }

    const int lane = t & 31, wid = t >> 5;
    #pragma unroll
    for (int g = 0; g < 12; ++g) {
        float m = fmaxf(fmaxf(mx[g][0], mx[g][1]), fmaxf(mx[g][2], mx[g][3]));
        #pragma unroll
        for (int o = 16; o > 0; o >>= 1) m = fmaxf(m, __shfl_xor_sync(0xffffffffu, m, o));
        if (lane == 0) wred[g * 8 + wid] = m;
    }
    __syncthreads();
    if (t < 12) {
        float m = wred[t * 8];
        #pragma unroll
        for (int w2 = 1; w2 < 8; ++w2) m = fmaxf(m, wred[t * 8 + w2]);
        gstat[t] = m;
    }
    __syncthreads();
    #pragma unroll
    for (int g = 0; g < 12; ++g) {
        float mg = gstat[g];
        float s = 0.f;
        #pragma unroll
        for (int r = 0; r < 4; ++r) { mx[g][r] = __expf(mx[g][r] - mg); s += mx[g][r]; }
        #pragma unroll
        for (int o = 16; o > 0; o >>= 1) s += __shfl_xor_sync(0xffffffffu, s, o);
        if (lane == 0) wred[g * 8 + wid] = s;
    }
    __syncthreads();
    if (t < 12) {
        float s = 0.f;
        #pragma unroll
        for (int w2 = 0; w2 < 8; ++w2) s += wred[t * 8 + w2];
        gstat[12 + t] = 1.0f / s;
    }
    __syncthreads();
    #pragma unroll
    for (int g = 0; g < 12; ++g) {
        float inv = gstat[12 + g];
        #pragma unroll
        for (int r = 0; r < 4; ++r) mx[g][r] *= inv;
    }
    #pragma unroll
    for (int h = 0; h < 12; ++h) {
        float o0 = 0.f, o1 = 0.f, o2 = 0.f, o3 = 0.f;
        #pragma unroll
        for (int g = 0; g < 12; ++g) {
            float p = post[g * 12 + h];
            o0 += mx[g][0] * p; o1 += mx[g][1] * p;
            o2 += mx[g][2] * p; o3 += mx[g][3] * p;
        }
        __half* dst = g_P + rowbase + (size_t)h * 1048576;
        dst[t]       = __float2half_rn(o0);
        dst[t + 256] = __float2half_rn(o1);
        dst[t + 512] = __float2half_rn(o2);
        dst[t + 768] = __float2half_rn(o3);
    }
}

// ---------------------------------------------------------------------------
// K4: O = attn(fp16) @ V(hi/lo) per (b,h) -> g_Ch/g_Cl. grid (8 it, 96 bh)
// ---------------------------------------------------------------------------
__global__ __launch_bounds__(256, 2) void k_av() {
    __shared__ __half As[128 * 40];
    __shared__ __half Vs[2 * 32 * 72];
    const int tid = threadIdx.x, lane = tid & 31, w = tid >> 5;
    const int it = blockIdx.x, bh = blockIdx.y;
    const int b = bh / 12, h = bh % 12;
    const __half* Pp  = g_P  + (size_t)bh * 1048576 + (size_t)it * 131072;
    const __half* Vhp = g_Vh + (size_t)bh * 65536;
    const __half* Vlp = g_Vl + (size_t)bh * 65536;
    const int wm = (w >> 1) * 32, wn = (w & 1) * 32;

    const int arow = tid >> 2, ac16 = tid & 3;
    const int vrow = tid >> 3, vc16 = tid & 7;

    const int lr = lane & 7, hs = (lane >> 3) & 1, kc = lane >> 4;
    const unsigned sa = (unsigned)__cvta_generic_to_shared(As);
    const unsigned sb = (unsigned)__cvta_generic_to_shared(Vs);
    const unsigned aaddr = sa + ((wm + hs * 8 + lr) * 40 + kc * 8) * 2;
    const unsigned baddr = sb + ((hs * 8 + lr) * 72 + wn + kc * 8) * 2;
    const unsigned VLOB = 32 * 72 * 2;

    float acc[2][4][4] = {};

    uint4 pa0 = *(const uint4*)(Pp + (size_t)arow * 1024 + ac16 * 8);
    uint4 pa1 = *(const uint4*)(Pp + (size_t)(arow + 64) * 1024 + ac16 * 8);
    uint4 pv0 = *(const uint4*)(Vhp + vrow * 64 + vc16 * 8);
    uint4 pv1 = *(const uint4*)(Vlp + vrow * 64 + vc16 * 8);

    for (int kt = 0; kt < 32; ++kt) {
        *(uint4*)&As[arow * 40 + ac16 * 8]        = pa0;
        *(uint4*)&As[(arow + 64) * 40 + ac16 * 8] = pa1;
        *(uint4*)&Vs[vrow * 72 + vc16 * 8]        = pv0;
        *(uint4*)&Vs[2304 + vrow * 72 + vc16 * 8] = pv1;
        __syncthreads();
        if (kt < 31) {
            pa0 = *(const uint4*)(Pp + (size_t)arow * 1024 + (kt + 1) * 32 + ac16 * 8);
            pa1 = *(const uint4*)(Pp + (size_t)(arow + 64) * 1024 + (kt + 1) * 32 + ac16 * 8);
            pv0 = *(const uint4*)(Vhp + (size_t)((kt + 1) * 32 + vrow) * 64 + vc16 * 8);
            pv1 = *(const uint4*)(Vlp + (size_t)((kt + 1) * 32 + vrow) * 64 + vc16 * 8);
        }
        #pragma unroll
        for (int kk = 0; kk < 32; kk += 16) {
            unsigned af[2][4], bvh[4][2], bvl[4][2];
            #pragma unroll
            for (int n2 = 0; n2 < 2; ++n2) {
                LDSM_X4T(bvh[2*n2][0], bvh[2*n2][1], bvh[2*n2+1][0], bvh[2*n2+1][1],
                         baddr + kk * 144 + n2 * 32);
                LDSM_X4T(bvl[2*n2][0], bvl[2*n2][1], bvl[2*n2+1][0], bvl[2*n2+1][1],
                         baddr + kk * 144 + n2 * 32 + VLOB);
            }
            #pragma unroll
            for (int mt = 0; mt < 2; ++mt)
                LDSM_X4(af[mt][0], af[mt][1], af[mt][2], af[mt][3],
                        aaddr + mt * 1280 + kk * 2);
            #pragma unroll
            for (int mt = 0; mt < 2; ++mt)
                #pragma unroll
                for (int nt = 0; nt < 4; ++nt) {
                    MMA16(acc[mt][nt], af[mt], bvh[nt]);
                    MMA16(acc[mt][nt], af[mt], bvl[nt]);
                }
        }
        __syncthreads();
    }

    const int g = lane >> 2, th = lane & 3;
    #pragma unroll
    for (int mt = 0; mt < 2; ++mt) {
        const int m = it * 128 + wm + mt * 16 + g;
        #pragma unroll
        for (int nt = 0; nt < 4; ++nt) {
            const int c = wn + nt * 8 + 2 * th;
            const size_t base = ((size_t)b * 1024 + m) * 768 + h * 64 + c;
            store_hl(g_Ch, g_Cl, base,             acc[mt][nt][0], acc[mt][nt][1]);
            store_hl(g_Ch, g_Cl, base + 8 * 768,   acc[mt][nt][2], acc[mt][nt][3]);
        }
    }
}

// ---------------------------------------------------------------------------
// K5: out = Ctx(hi/lo fp16) @ Wo + bo. grid (6, 64)
// ---------------------------------------------------------------------------
__global__ __launch_bounds__(256, 2) void k_out(const float* __restrict__ Wo,
                                                const float* __restrict__ bo,
                                                float* __restrict__ out) {
    __shared__ __half As[2 * 128 * 24];
    __shared__ __half Bs[2 * 16 * 136];
    const int tid = threadIdx.x, lane = tid & 31, w = tid >> 5;
    const int bx = blockIdx.x, by = blockIdx.y;
    const float* Bp = Wo + bx * 128;
    const int wm = (w >> 2) * 64, wn = (w & 3) * 32;

    const int arow = tid >> 1, ac16 = tid & 1;
    const int bk = tid >> 4, bn4 = (tid & 15) * 4;
    const __half* Chp = g_Ch + (size_t)by * 128 * 768;
    const __half* Clp = g_Cl + (size_t)by * 128 * 768;

    const int lr = lane & 7, hs = (lane >> 3) & 1, kc = lane >> 4;
    const unsigned sa = (unsigned)__cvta_generic_to_shared(As);
    const unsigned sb = (unsigned)__cvta_generic_to_shared(Bs);
    const unsigned aaddr = sa + ((wm + hs * 8 + lr) * 24 + kc * 8) * 2;
    const unsigned baddr = sb + ((hs * 8 + lr) * 136 + wn + kc * 8) * 2;
    const unsigned ALO = 128 * 24 * 2, BLO = 16 * 136 * 2;

    float acc[4][4][4] = {};

    uint4 rah = *(const uint4*)(Chp + (size_t)arow * 768 + ac16 * 8);
    uint4 ral = *(const uint4*)(Clp + (size_t)arow * 768 + ac16 * 8);
    float4 rb0 = *(const float4*)(Bp + (size_t)bk * 768 + bn4);
    float4 rb1 = *(const float4*)(Bp + (size_t)bk * 768 + bn4 + 64);

    for (int kt = 0; kt < 48; ++kt) {
        *(uint4*)&As[arow * 24 + ac16 * 8]        = rah;
        *(uint4*)&As[3072 + arow * 24 + ac16 * 8] = ral;
        uint2 h, l;
        split4(rb0, h, l);
        *(uint2*)&Bs[bk * 136 + bn4] = h;          *(uint2*)&Bs[2176 + bk * 136 + bn4] = l;
        split4(rb1, h, l);
        *(uint2*)&Bs[bk * 136 + bn4 + 64] = h;     *(uint2*)&Bs[2176 + bk * 136 + bn4 + 64] = l;
        __syncthreads();
        if (kt < 47) {
            rah = *(const uint4*)(Chp + (size_t)arow * 768 + (kt + 1) * 16 + ac16 * 8);
            ral = *(const uint4*)(Clp + (size_t)arow * 768 + (kt + 1) * 16 + ac16 * 8);
            rb0 = *(const float4*)(Bp + (size_t)((kt + 1) * 16 + bk) * 768 + bn4);
            rb1 = *(const float4*)(Bp + (size_t)((kt + 1) * 16 + bk) * 768 + bn4 + 64);
        }
        unsigned af[4][4], bh[4][2], bl[4][2];
        #pragma unroll
        for (int mt = 0; mt < 4; ++mt)
            LDSM_X4(af[mt][0], af[mt][1], af[mt][2], af[mt][3], aaddr + mt * 768);
        #pragma unroll
        for (int n2 = 0; n2 < 2; ++n2) {
            LDSM_X4T(bh[2*n2][0], bh[2*n2][1], bh[2*n2+1][0], bh[2*n2+1][1], baddr + n2 * 32);
            LDSM_X4T(bl[2*n2][0], bl[2*n2][1], bl[2*n2+1][0], bl[2*n2+1][1], baddr + n2 * 32 + BLO);
        }
        #pragma unroll
        for (int mt = 0; mt < 4; ++mt)
            #pragma unroll
            for (int nt = 0; nt < 4; ++nt) {
                MMA16(acc[mt][nt], af[mt], bh[nt]);
                MMA16(acc[mt][nt], af[mt], bl[nt]);
            }
        #pragma unroll
        for (int mt = 0; mt < 4; ++mt)
            LDSM_X4(af[mt][0], af[mt][1], af[mt][2], af[mt][3], aaddr + mt * 768 + ALO);
        #pragma unroll
        for (int mt = 0; mt < 4; ++mt)
            #pragma unroll
            for (int nt = 0; nt < 4; ++nt)
                MMA16(acc[mt][nt], af[mt], bh[nt]);
        __syncthreads();
    }

    const int g = lane >> 2, th = lane & 3;
    #pragma unroll
    for (int nt = 0; nt < 4; ++nt) {
        const int c = bx * 128 + wn + nt * 8 + 2 * th;
        const float b0v = bo[c], b1v = bo[c + 1];
        #pragma unroll
        for (int mt = 0; mt < 4; ++mt) {
            const int m = by * 128 + wm + mt * 16 + g;
            *(float2*)(out + (size_t)m * 768 + c) =
                make_float2(acc[mt][nt][0] + b0v, acc[mt][nt][1] + b1v);
            *(float2*)(out + (size_t)(m + 8) * 768 + c) =
                make_float2(acc[mt][nt][2] + b0v, acc[mt][nt][3] + b1v);
        }
    }
}

// ---------------------------------------------------------------------------
extern "C" void kernel_launch(void* const* d_in, const int* in_sizes, int n_in,
                              void* d_out, int out_size) {
    const float* x     = (const float*)d_in[0];
    const float* Wq    = (const float*)d_in[1];
    const float* Wkv   = (const float*)d_in[2];
    const float* mpre  = (const float*)d_in[3];
    const float* mpost = (const float*)d_in[4];
    const float* Wo    = (const float*)d_in[5];
    const float* bo    = (const float*)d_in[6];
    float* out = (float*)d_out;

    k_qkv    <<<dim3(18, 64),   256>>>(x, Wq, Wkv);
    k_dots   <<<dim3(8, 8, 96), 256>>>();
    k_mixsoft<<<8192,           256>>>(mpre, mpost);
    k_av     <<<dim3(8, 96),    256>>>();
    k_out    <<<dim3(6, 64),    256>>>(Wo, bo, out);
}

// round 7
// speedup vs baseline: 3.7523x; 1.1008x over previous
#include <cuda_runtime.h>
#include <cuda_fp16.h>
#include <math.h>

#define Bb 8
#define Nn 1024
#define Hh 12

#define QKVSZ ((size_t)Bb*Hh*Nn*64)

// Scratch (static device globals)
__device__ __half g_Qh[QKVSZ], g_Ql[QKVSZ];
__device__ __half g_Kh[QKVSZ], g_Kl[QKVSZ];
__device__ __half g_Vh[QKVSZ], g_Vl[QKVSZ];
__device__ __half g_S[(size_t)Bb*Hh*Nn*Nn];   // fp16 raw logits
__device__ __half g_P[(size_t)Bb*Hh*Nn*Nn];   // fp16 post-mixed attn
__device__ __half g_Ch[(size_t)Bb*Nn*768], g_Cl[(size_t)Bb*Nn*768];

// ---------------------------------------------------------------------------
__device__ __forceinline__ void split2(float a, float b, unsigned &h, unsigned &l) {
    __half ha = __float2half_rn(a), hb = __float2half_rn(b);
    __half2 H = __halves2half2(ha, hb);
    __half2 L = __halves2half2(__float2half_rn(a - __half2float(ha)),
                               __float2half_rn(b - __half2float(hb)));
    h = *(unsigned*)&H; l = *(unsigned*)&L;
}
__device__ __forceinline__ void split4(float4 v, uint2 &h, uint2 &l) {
    split2(v.x, v.y, h.x, l.x); split2(v.z, v.w, h.y, l.y);
}
__device__ __forceinline__ uint2 pack4h(float4 v) {
    __half2 a = __floats2half2_rn(v.x, v.y);
    __half2 b = __floats2half2_rn(v.z, v.w);
    uint2 r; r.x = *(unsigned*)&a; r.y = *(unsigned*)&b; return r;
}
__device__ __forceinline__ void store_hl(__half* Gh, __half* Gl, size_t idx,
                                         float v0, float v1) {
    __half h0 = __float2half_rn(v0), h1 = __float2half_rn(v1);
    __half l0 = __float2half_rn(v0 - __half2float(h0));
    __half l1 = __float2half_rn(v1 - __half2float(h1));
    *(__half2*)(Gh + idx) = __halves2half2(h0, h1);
    *(__half2*)(Gl + idx) = __halves2half2(l0, l1);
}

#define LDSM_X4(r0, r1, r2, r3, a) \
  asm volatile("ldmatrix.sync.aligned.m8n8.x4.shared.b16 {%0,%1,%2,%3},[%4];" \
               : "=r"(r0), "=r"(r1), "=r"(r2), "=r"(r3) : "r"(a))
#define LDSM_X4T(r0, r1, r2, r3, a) \
  asm volatile("ldmatrix.sync.aligned.m8n8.x4.trans.shared.b16 {%0,%1,%2,%3},[%4];" \
               : "=r"(r0), "=r"(r1), "=r"(r2), "=r"(r3) : "r"(a))
#define MMA16(c, a, b) \
  asm volatile("mma.sync.aligned.m16n8k16.row.col.f32.f16.f16.f32 " \
               "{%0,%1,%2,%3},{%4,%5,%6,%7},{%8,%9},{%0,%1,%2,%3};" \
               : "+f"(c[0]), "+f"(c[1]), "+f"(c[2]), "+f"(c[3]) \
               : "r"(a[0]), "r"(a[1]), "r"(a[2]), "r"(a[3]), "r"(b[0]), "r"(b[1]))

// ---------------------------------------------------------------------------
// K1: QKV projection. x[8192,768] @ fp16([Wq|Wkv]) -> pre-split hi/lo Q/K/V.
// 2 mma passes: Ah*Bh + Al*Bh (W quantized to fp16). Double-buffered smem.
// grid (18, 64). Q gets the 1/8 softmax scale folded in (exact).
// ---------------------------------------------------------------------------
__global__ __launch_bounds__(256, 2) void k_qkv(const float* __restrict__ x,
                                                const float* __restrict__ Wq,
                                                const float* __restrict__ Wkv) {
    __shared__ __half As[2][2 * 128 * 24];
    __shared__ __half Bs[2][16 * 136];
    const int tid = threadIdx.x, lane = tid & 31, w = tid >> 5;
    const int bx = blockIdx.x, by = blockIdx.y;
    const int nglob = bx * 128;
    const float* Bp = (nglob < 768) ? (Wq + nglob) : (Wkv + (nglob - 768));
    const int ldb = (nglob < 768) ? 768 : 1536;
    const int wm = (w >> 2) * 64, wn = (w & 3) * 32;

    const int ar = tid >> 2, ak4 = (tid & 3) * 4;
    const int bk = tid >> 4, bn4 = (tid & 15) * 4;
    const float* Ap = x + ((size_t)by * 128 + ar) * 768 + ak4;

    const int lr = lane & 7, hs = (lane >> 3) & 1, kc = lane >> 4;
    const unsigned sa = (unsigned)__cvta_generic_to_shared(&As[0][0]);
    const unsigned sb = (unsigned)__cvta_generic_to_shared(&Bs[0][0]);
    const unsigned aaddr = sa + ((wm + hs * 8 + lr) * 24 + kc * 8) * 2;
    const unsigned baddr = sb + ((hs * 8 + lr) * 136 + wn + kc * 8) * 2;
    const unsigned ALO = 128 * 24 * 2;        // lo-plane byte offset within buffer
    const unsigned ABUF = 2 * 128 * 24 * 2;   // buffer byte stride
    const unsigned BBUF = 16 * 136 * 2;

    float acc[4][4][4] = {};

    float4 ra0 = *(const float4*)(Ap);
    float4 ra1 = *(const float4*)(Ap + (size_t)64 * 768);
    float4 rb0 = *(const float4*)(Bp + (size_t)bk * ldb + bn4);
    float4 rb1 = *(const float4*)(Bp + (size_t)bk * ldb + bn4 + 64);
    {
        uint2 h, l;
        split4(ra0, h, l);
        *(uint2*)&As[0][ar * 24 + ak4] = h;        *(uint2*)&As[0][3072 + ar * 24 + ak4] = l;
        split4(ra1, h, l);
        *(uint2*)&As[0][(ar + 64) * 24 + ak4] = h; *(uint2*)&As[0][3072 + (ar + 64) * 24 + ak4] = l;
        *(uint2*)&Bs[0][bk * 136 + bn4]      = pack4h(rb0);
        *(uint2*)&Bs[0][bk * 136 + bn4 + 64] = pack4h(rb1);
    }
    __syncthreads();

    for (int kt = 0; kt < 48; ++kt) {
        const int cur = kt & 1;
        if (kt < 47) {
            ra0 = *(const float4*)(Ap + (kt + 1) * 16);
            ra1 = *(const float4*)(Ap + (size_t)64 * 768 + (kt + 1) * 16);
            rb0 = *(const float4*)(Bp + (size_t)((kt + 1) * 16 + bk) * ldb + bn4);
            rb1 = *(const float4*)(Bp + (size_t)((kt + 1) * 16 + bk) * ldb + bn4 + 64);
        }
        unsigned af[4][4], bh[4][2];
        #pragma unroll
        for (int n2 = 0; n2 < 2; ++n2)
            LDSM_X4T(bh[2*n2][0], bh[2*n2][1], bh[2*n2+1][0], bh[2*n2+1][1],
                     baddr + cur * BBUF + n2 * 32);
        #pragma unroll
        for (int mt = 0; mt < 4; ++mt)
            LDSM_X4(af[mt][0], af[mt][1], af[mt][2], af[mt][3],
                    aaddr + cur * ABUF + mt * 768);
        #pragma unroll
        for (int mt = 0; mt < 4; ++mt)
            #pragma unroll
            for (int nt = 0; nt < 4; ++nt)
                MMA16(acc[mt][nt], af[mt], bh[nt]);
        #pragma unroll
        for (int mt = 0; mt < 4; ++mt)
            LDSM_X4(af[mt][0], af[mt][1], af[mt][2], af[mt][3],
                    aaddr + cur * ABUF + mt * 768 + ALO);
        #pragma unroll
        for (int mt = 0; mt < 4; ++mt)
            #pragma unroll
            for (int nt = 0; nt < 4; ++nt)
                MMA16(acc[mt][nt], af[mt], bh[nt]);
        if (kt < 47) {
            const int nb = cur ^ 1;
            uint2 h, l;
            split4(ra0, h, l);
            *(uint2*)&As[nb][ar * 24 + ak4] = h;        *(uint2*)&As[nb][3072 + ar * 24 + ak4] = l;
            split4(ra1, h, l);
            *(uint2*)&As[nb][(ar + 64) * 24 + ak4] = h; *(uint2*)&As[nb][3072 + (ar + 64) * 24 + ak4] = l;
            *(uint2*)&Bs[nb][bk * 136 + bn4]      = pack4h(rb0);
            *(uint2*)&Bs[nb][bk * 136 + bn4 + 64] = pack4h(rb1);
        }
        __syncthreads();
    }

    const int g = lane >> 2, th = lane & 3;
    #pragma unroll
    for (int nt = 0; nt < 4; ++nt) {
        const int col = nglob + wn + nt * 8 + 2 * th;
        const int mat = col / 768;
        const int within = col - mat * 768;
        const int head = within >> 6, d = within & 63;
        __half* Gh = (mat == 0) ? g_Qh : (mat == 1) ? g_Kh : g_Vh;
        __half* Gl = (mat == 0) ? g_Ql : (mat == 1) ? g_Kl : g_Vl;
        const float sc = (mat == 0) ? 0.125f : 1.0f;
        #pragma unroll
        for (int mt = 0; mt < 4; ++mt) {
            const int m0 = by * 128 + wm + mt * 16 + g;
            const int b = m0 >> 10, nr = m0 & 1023;
            const size_t base = (((size_t)b * 12 + head) * 1024 + nr) * 64 + d;
            store_hl(Gh, Gl, base,            acc[mt][nt][0] * sc, acc[mt][nt][1] * sc);
            store_hl(Gh, Gl, base + 8 * 64,   acc[mt][nt][2] * sc, acc[mt][nt][3] * sc);
        }
    }
}

// ---------------------------------------------------------------------------
// K2: logits = (Q/8) @ K^T per (b,h), pre-split fp16 inputs -> fp16 g_S.
// grid (8,8,96). (unchanged from round 6)
// ---------------------------------------------------------------------------
__global__ __launch_bounds__(256, 2) void k_dots() {
    __shared__ __half Qs[2 * 128 * 40];
    __shared__ __half Ks[2 * 128 * 40];
    const int tid = threadIdx.x, lane = tid & 31, w = tid >> 5;
    const int jt = blockIdx.x, it = blockIdx.y, bh = blockIdx.z;
    const __half* Qhp = g_Qh + (size_t)bh * 65536 + (size_t)it * 128 * 64;
    const __half* Qlp = g_Ql + (size_t)bh * 65536 + (size_t)it * 128 * 64;
    const __half* Khp = g_Kh + (size_t)bh * 65536 + (size_t)jt * 128 * 64;
    const __half* Klp = g_Kl + (size_t)bh * 65536 + (size_t)jt * 128 * 64;
    __half* Sp = g_S + (size_t)bh * Nn * Nn;
    const int wm = (w >> 2) * 64, wn = (w & 3) * 32;

    const int lr = lane & 7, hs = (lane >> 3) & 1, kc = lane >> 4;
    const unsigned sq = (unsigned)__cvta_generic_to_shared(Qs);
    const unsigned sk = (unsigned)__cvta_generic_to_shared(Ks);
    const unsigned aaddr = sq + ((wm + hs * 8 + lr) * 40 + kc * 8) * 2;
    const unsigned kaddr = sk + ((wn + hs * 8 + lr) * 40 + kc * 8) * 2;
    const unsigned PLO = 128 * 40 * 2;

    float acc[4][4][4] = {};

    for (int kt = 0; kt < 2; ++kt) {
        #pragma unroll
        for (int j = 0; j < 2; ++j) {
            const int u = j * 256 + tid;
            const int row = u >> 2, c16 = u & 3;
            const int goff = row * 64 + kt * 32 + c16 * 8;
            const int soff = row * 40 + c16 * 8;
            *(uint4*)&Qs[soff]        = *(const uint4*)(Qhp + goff);
            *(uint4*)&Qs[5120 + soff] = *(const uint4*)(Qlp + goff);
            *(uint4*)&Ks[soff]        = *(const uint4*)(Khp + goff);
            *(uint4*)&Ks[5120 + soff] = *(const uint4*)(Klp + goff);
        }
        __syncthreads();
        #pragma unroll
        for (int kk = 0; kk < 32; kk += 16) {
            unsigned bkh[4][2], bkl[4][2], af[4][4];
            #pragma unroll
            for (int n2 = 0; n2 < 2; ++n2) {
                LDSM_X4(bkh[2*n2][0], bkh[2*n2+1][0], bkh[2*n2][1], bkh[2*n2+1][1],
                        kaddr + n2 * 1280 + kk * 2);
                LDSM_X4(bkl[2*n2][0], bkl[2*n2+1][0], bkl[2*n2][1], bkl[2*n2+1][1],
                        kaddr + n2 * 1280 + kk * 2 + PLO);
            }
            #pragma unroll
            for (int mt = 0; mt < 4; ++mt)
                LDSM_X4(af[mt][0], af[mt][1], af[mt][2], af[mt][3],
                        aaddr + mt * 1280 + kk * 2);
            #pragma unroll
            for (int mt = 0; mt < 4; ++mt)
                #pragma unroll
                for (int nt = 0; nt < 4; ++nt) {
                    MMA16(acc[mt][nt], af[mt], bkh[nt]);
                    MMA16(acc[mt][nt], af[mt], bkl[nt]);
                }
            #pragma unroll
            for (int mt = 0; mt < 4; ++mt)
                LDSM_X4(af[mt][0], af[mt][1], af[mt][2], af[mt][3],
                        aaddr + mt * 1280 + kk * 2 + PLO);
            #pragma unroll
            for (int mt = 0; mt < 4; ++mt)
                #pragma unroll
                for (int nt = 0; nt < 4; ++nt)
                    MMA16(acc[mt][nt], af[mt], bkh[nt]);
        }
        __syncthreads();
    }

    const int g = lane >> 2, th = lane & 3;
    #pragma unroll
    for (int mt = 0; mt < 4; ++mt) {
        const int m = it * 128 + wm + mt * 16 + g;
        #pragma unroll
        for (int nt = 0; nt < 4; ++nt) {
            const int c = jt * 128 + wn + nt * 8 + 2 * th;
            *(__half2*)(Sp + (size_t)m * 1024 + c) =
                __floats2half2_rn(acc[mt][nt][0], acc[mt][nt][1]);
            *(__half2*)(Sp + (size_t)(m + 8) * 1024 + c) =
                __floats2half2_rn(acc[mt][nt][2], acc[mt][nt][3]);
        }
    }
}

// ---------------------------------------------------------------------------
// K3: mix_pre -> softmax -> mix_post; reads fp16 g_S, writes fp16 g_P.
// (unchanged from round 6)
// ---------------------------------------------------------------------------
__global__ __launch_bounds__(256) void k_mixsoft(const float* __restrict__ mix_pre,
                                                 const float* __restrict__ mix_post) {
    __shared__ __half raw[12 * 1024];
    __shared__ float pre[144], post[144];
    __shared__ float wred[96];
    __shared__ float gstat[24];
    const int t = threadIdx.x;
    const int b = blockIdx.x >> 10, i = blockIdx.x & 1023;
    if (t < 144) { pre[t] = mix_pre[t]; post[t] = mix_post[t]; }
    const size_t rowbase = (size_t)b * 12 * 1048576 + (size_t)i * 1024;

    #pragma unroll
    for (int u = 0; u < 6; ++u) {
        const int v = u * 256 + t;
        const int h = v >> 7;
        const int j8 = (v & 127) * 8;
        *(uint4*)&raw[h * 1024 + j8] =
            *(const uint4*)(g_S + rowbase + (size_t)h * 1048576 + j8);
    }
    __syncthreads();

    float mx[12][4];
    #pragma unroll
    for (int g = 0; g < 12; ++g)
        mx[g][0] = mx[g][1] = mx[g][2] = mx[g][3] = 0.f;

    #pragma unroll
    for (int c = 0; c < 2; ++c) {
        float rv[12][2];
        #pragma unroll
        for (int h = 0; h < 12; ++h) {
            rv[h][0] = __half2float(raw[h * 1024 + c * 512 + t]);
            rv[h][1] = __half2float(raw[h * 1024 + c * 512 + t + 256]);
        }
        #pragma unroll
        for (int g = 0; g < 12; ++g) {
            float a0 = mx[g][c * 2], a1 = mx[g][c * 2 + 1];
            #pragma unroll
            for (int h = 0; h < 12; ++h) {
                float p = pre[h * 12 + g];
                a0 += rv[h][0] * p;
                a1 += rv[h][1] * p;
            }
            mx[g][c * 2] = a0; mx[g][c * 2 + 1] = a1;
        }
    }

    const int lane = t & 31, wid = t >> 5;
    #pragma unroll
    for (int g = 0; g < 12; ++g) {
        float m = fmaxf(fmaxf(mx[g][0], mx[g][1]), fmaxf(mx[g][2], mx[g][3]));
        #pragma unroll
        for (int o = 16; o > 0; o >>= 1) m = fmaxf(m, __shfl_xor_sync(0xffffffffu, m, o));
        if (lane == 0) wred[g * 8 + wid] = m;
    }
    __syncthreads();
    if (t < 12) {
        float m = wred[t * 8];
        #pragma unroll
        for (int w2 = 1; w2 < 8; ++w2) m = fmaxf(m, wred[t * 8 + w2]);
        gstat[t] = m;
    }
    __syncthreads();
    #pragma unroll
    for (int g = 0; g < 12; ++g) {
        float mg = gstat[g];
        float s = 0.f;
        #pragma unroll
        for (int r = 0; r < 4; ++r) { mx[g][r] = __expf(mx[g][r] - mg); s += mx[g][r]; }
        #pragma unroll
        for (int o = 16; o > 0; o >>= 1) s += __shfl_xor_sync(0xffffffffu, s, o);
        if (lane == 0) wred[g * 8 + wid] = s;
    }
    __syncthreads();
    if (t < 12) {
        float s = 0.f;
        #pragma unroll
        for (int w2 = 0; w2 < 8; ++w2) s += wred[t * 8 + w2];
        gstat[12 + t] = 1.0f / s;
    }
    __syncthreads();
    #pragma unroll
    for (int g = 0; g < 12; ++g) {
        float inv = gstat[12 + g];
        #pragma unroll
        for (int r = 0; r < 4; ++r) mx[g][r] *= inv;
    }
    #pragma unroll
    for (int h = 0; h < 12; ++h) {
        float o0 = 0.f, o1 = 0.f, o2 = 0.f, o3 = 0.f;
        #pragma unroll
        for (int g = 0; g < 12; ++g) {
            float p = post[g * 12 + h];
            o0 += mx[g][0] * p; o1 += mx[g][1] * p;
            o2 += mx[g][2] * p; o3 += mx[g][3] * p;
        }
        __half* dst = g_P + rowbase + (size_t)h * 1048576;
        dst[t]       = __float2half_rn(o0);
        dst[t + 256] = __float2half_rn(o1);
        dst[t + 512] = __float2half_rn(o2);
        dst[t + 768] = __float2half_rn(o3);
    }
}

// ---------------------------------------------------------------------------
// K4: O = attn(fp16) @ V(hi/lo) per (b,h) -> g_Ch/g_Cl. grid (8 it, 96 bh)
// Double-buffered smem, one sync per k-chunk.
// ---------------------------------------------------------------------------
__global__ __launch_bounds__(256, 2) void k_av() {
    __shared__ __half As[2][128 * 40];
    __shared__ __half Vs[2][2 * 32 * 72];
    const int tid = threadIdx.x, lane = tid & 31, w = tid >> 5;
    const int it = blockIdx.x, bh = blockIdx.y;
    const int b = bh / 12, h = bh % 12;
    const __half* Pp  = g_P  + (size_t)bh * 1048576 + (size_t)it * 131072;
    const __half* Vhp = g_Vh + (size_t)bh * 65536;
    const __half* Vlp = g_Vl + (size_t)bh * 65536;
    const int wm = (w >> 1) * 32, wn = (w & 1) * 32;

    const int arow = tid >> 2, ac16 = tid & 3;
    const int vrow = tid >> 3, vc16 = tid & 7;

    const int lr = lane & 7, hs = (lane >> 3) & 1, kc = lane >> 4;
    const unsigned sa = (unsigned)__cvta_generic_to_shared(&As[0][0]);
    const unsigned sb = (unsigned)__cvta_generic_to_shared(&Vs[0][0]);
    const unsigned aaddr = sa + ((wm + hs * 8 + lr) * 40 + kc * 8) * 2;
    const unsigned baddr = sb + ((hs * 8 + lr) * 72 + wn + kc * 8) * 2;
    const unsigned ABUF = 128 * 40 * 2;      // 10240
    const unsigned VBUF = 2 * 32 * 72 * 2;   // 9216
    const unsigned VLOB = 32 * 72 * 2;       // 4608

    float acc[2][4][4] = {};

    uint4 pa0 = *(const uint4*)(Pp + (size_t)arow * 1024 + ac16 * 8);
    uint4 pa1 = *(const uint4*)(Pp + (size_t)(arow + 64) * 1024 + ac16 * 8);
    uint4 pv0 = *(const uint4*)(Vhp + vrow * 64 + vc16 * 8);
    uint4 pv1 = *(const uint4*)(Vlp + vrow * 64 + vc16 * 8);
    {
        *(uint4*)&As[0][arow * 40 + ac16 * 8]        = pa0;
        *(uint4*)&As[0][(arow + 64) * 40 + ac16 * 8] = pa1;
        *(uint4*)&Vs[0][vrow * 72 + vc16 * 8]        = pv0;
        *(uint4*)&Vs[0][2304 + vrow * 72 + vc16 * 8] = pv1;
    }
    __syncthreads();

    for (int kt = 0; kt < 32; ++kt) {
        const int cur = kt & 1;
        if (kt < 31) {
            pa0 = *(const uint4*)(Pp + (size_t)arow * 1024 + (kt + 1) * 32 + ac16 * 8);
            pa1 = *(const uint4*)(Pp + (size_t)(arow + 64) * 1024 + (kt + 1) * 32 + ac16 * 8);
            pv0 = *(const uint4*)(Vhp + (size_t)((kt + 1) * 32 + vrow) * 64 + vc16 * 8);
            pv1 = *(const uint4*)(Vlp + (size_t)((kt + 1) * 32 + vrow) * 64 + vc16 * 8);
        }
        #pragma unroll
        for (int kk = 0; kk < 32; kk += 16) {
            unsigned af[2][4], bvh[4][2], bvl[4][2];
            #pragma unroll
            for (int n2 = 0; n2 < 2; ++n2) {
                LDSM_X4T(bvh[2*n2][0], bvh[2*n2][1], bvh[2*n2+1][0], bvh[2*n2+1][1],
                         baddr + cur * VBUF + kk * 144 + n2 * 32);
                LDSM_X4T(bvl[2*n2][0], bvl[2*n2][1], bvl[2*n2+1][0], bvl[2*n2+1][1],
                         baddr + cur * VBUF + kk * 144 + n2 * 32 + VLOB);
            }
            #pragma unroll
            for (int mt = 0; mt < 2; ++mt)
                LDSM_X4(af[mt][0], af[mt][1], af[mt][2], af[mt][3],
                        aaddr + cur * ABUF + mt * 1280 + kk * 2);
            #pragma unroll
            for (int mt = 0; mt < 2; ++mt)
                #pragma unroll
                for (int nt = 0; nt < 4; ++nt) {
                    MMA16(acc[mt][nt], af[mt], bvh[nt]);
                    MMA16(acc[mt][nt], af[mt], bvl[nt]);
                }
        }
        if (kt < 31) {
            const int nb = cur ^ 1;
            *(uint4*)&As[nb][arow * 40 + ac16 * 8]        = pa0;
            *(uint4*)&As[nb][(arow + 64) * 40 + ac16 * 8] = pa1;
            *(uint4*)&Vs[nb][vrow * 72 + vc16 * 8]        = pv0;
            *(uint4*)&Vs[nb][2304 + vrow * 72 + vc16 * 8] = pv1;
        }
        __syncthreads();
    }

    const int g = lane >> 2, th = lane & 3;
    #pragma unroll
    for (int mt = 0; mt < 2; ++mt) {
        const int m = it * 128 + wm + mt * 16 + g;
        #pragma unroll
        for (int nt = 0; nt < 4; ++nt) {
            const int c = wn + nt * 8 + 2 * th;
            const size_t base = ((size_t)b * 1024 + m) * 768 + h * 64 + c;
            store_hl(g_Ch, g_Cl, base,             acc[mt][nt][0], acc[mt][nt][1]);
            store_hl(g_Ch, g_Cl, base + 8 * 768,   acc[mt][nt][2], acc[mt][nt][3]);
        }
    }
}

// ---------------------------------------------------------------------------
// K5: out = Ctx(hi/lo) @ fp16(Wo) + bo. 2 mma passes, double buffered.
// grid (6, 64)
// ---------------------------------------------------------------------------
__global__ __launch_bounds__(256, 2) void k_out(const float* __restrict__ Wo,
                                                const float* __restrict__ bo,
                                                float* __restrict__ out) {
    __shared__ __half As[2][2 * 128 * 24];
    __shared__ __half Bs[2][16 * 136];
    const int tid = threadIdx.x, lane = tid & 31, w = tid >> 5;
    const int bx = blockIdx.x, by = blockIdx.y;
    const float* Bp = Wo + bx * 128;
    const int wm = (w >> 2) * 64, wn = (w & 3) * 32;

    const int arow = tid >> 1, ac16 = tid & 1;
    const int bk = tid >> 4, bn4 = (tid & 15) * 4;
    const __half* Chp = g_Ch + (size_t)by * 128 * 768;
    const __half* Clp = g_Cl + (size_t)by * 128 * 768;

    const int lr = lane & 7, hs = (lane >> 3) & 1, kc = lane >> 4;
    const unsigned sa = (unsigned)__cvta_generic_to_shared(&As[0][0]);
    const unsigned sb = (unsigned)__cvta_generic_to_shared(&Bs[0][0]);
    const unsigned aaddr = sa + ((wm + hs * 8 + lr) * 24 + kc * 8) * 2;
    const unsigned baddr = sb + ((hs * 8 + lr) * 136 + wn + kc * 8) * 2;
    const unsigned ALO = 128 * 24 * 2;
    const unsigned ABUF = 2 * 128 * 24 * 2;
    const unsigned BBUF = 16 * 136 * 2;

    float acc[4][4][4] = {};

    uint4 rah = *(const uint4*)(Chp + (size_t)arow * 768 + ac16 * 8);
    uint4 ral = *(const uint4*)(Clp + (size_t)arow * 768 + ac16 * 8);
    float4 rb0 = *(const float4*)(Bp + (size_t)bk * 768 + bn4);
    float4 rb1 = *(const float4*)(Bp + (size_t)bk * 768 + bn4 + 64);
    {
        *(uint4*)&As[0][arow * 24 + ac16 * 8]        = rah;
        *(uint4*)&As[0][3072 + arow * 24 + ac16 * 8] = ral;
        *(uint2*)&Bs[0][bk * 136 + bn4]      = pack4h(rb0);
        *(uint2*)&Bs[0][bk * 136 + bn4 + 64] = pack4h(rb1);
    }
    __syncthreads();

    for (int kt = 0; kt < 48; ++kt) {
        const int cur = kt & 1;
        if (kt < 47) {
            rah = *(const uint4*)(Chp + (size_t)arow * 768 + (kt + 1) * 16 + ac16 * 8);
            ral = *(const uint4*)(Clp + (size_t)arow * 768 + (kt + 1) * 16 + ac16 * 8);
            rb0 = *(const float4*)(Bp + (size_t)((kt + 1) * 16 + bk) * 768 + bn4);
            rb1 = *(const float4*)(Bp + (size_t)((kt + 1) * 16 + bk) * 768 + bn4 + 64);
        }
        unsigned af[4][4], bh[4][2];
        #pragma unroll
        for (int n2 = 0; n2 < 2; ++n2)
            LDSM_X4T(bh[2*n2][0], bh[2*n2][1], bh[2*n2+1][0], bh[2*n2+1][1],
                     baddr + cur * BBUF + n2 * 32);
        #pragma unroll
        for (int mt = 0; mt < 4; ++mt)
            LDSM_X4(af[mt][0], af[mt][1], af[mt][2], af[mt][3],
                    aaddr + cur * ABUF + mt * 768);
        #pragma unroll
        for (int mt = 0; mt < 4; ++mt)
            #pragma unroll
            for (int nt = 0; nt < 4; ++nt)
                MMA16(acc[mt][nt], af[mt], bh[nt]);
        #pragma unroll
        for (int mt = 0; mt < 4; ++mt)
            LDSM_X4(af[mt][0], af[mt][1], af[mt][2], af[mt][3],
                    aaddr + cur * ABUF + mt * 768 + ALO);
        #pragma unroll
        for (int mt = 0; mt < 4; ++mt)
            #pragma unroll
            for (int nt = 0; nt < 4; ++nt)
                MMA16(acc[mt][nt], af[mt], bh[nt]);
        if (kt < 47) {
            const int nb = cur ^ 1;
            *(uint4*)&As[nb][arow * 24 + ac16 * 8]        = rah;
            *(uint4*)&As[nb][3072 + arow * 24 + ac16 * 8] = ral;
            *(uint2*)&Bs[nb][bk * 136 + bn4]      = pack4h(rb0);
            *(uint2*)&Bs[nb][bk * 136 + bn4 + 64] = pack4h(rb1);
        }
        __syncthreads();
    }

    const int g = lane >> 2, th = lane & 3;
    #pragma unroll
    for (int nt = 0; nt < 4; ++nt) {
        const int c = bx * 128 + wn + nt * 8 + 2 * th;
        const float b0v = bo[c], b1v = bo[c + 1];
        #pragma unroll
        for (int mt = 0; mt < 4; ++mt) {
            const int m = by * 128 + wm + mt * 16 + g;
            *(float2*)(out + (size_t)m * 768 + c) =
                make_float2(acc[mt][nt][0] + b0v, acc[mt][nt][1] + b1v);
            *(float2*)(out + (size_t)(m + 8) * 768 + c) =
                make_float2(acc[mt][nt][2] + b0v, acc[mt][nt][3] + b1v);
        }
    }
}

// ---------------------------------------------------------------------------
extern "C" void kernel_launch(void* const* d_in, const int* in_sizes, int n_in,
                              void* d_out, int out_size) {
    const float* x     = (const float*)d_in[0];
    const float* Wq    = (const float*)d_in[1];
    const float* Wkv   = (const float*)d_in[2];
    const float* mpre  = (const float*)d_in[3];
    const float* mpost = (const float*)d_in[4];
    const float* Wo    = (const float*)d_in[5];
    const float* bo    = (const float*)d_in[6];
    float* out = (float*)d_out;

    k_qkv    <<<dim3(18, 64),   256>>>(x, Wq, Wkv);
    k_dots   <<<dim3(8, 8, 96), 256>>>();
    k_mixsoft<<<8192,           256>>>(mpre, mpost);
    k_av     <<<dim3(8, 96),    256>>>();
    k_out    <<<dim3(6, 64),    256>>>(Wo, bo, out);
}